// round 10
// baseline (speedup 1.0000x reference)
#include <cuda_runtime.h>
#include <math.h>
#include <stdint.h>

// Problem constants
constexpr int Bc  = 2;
constexpr int Tt  = 2048;
constexpr int Dd  = 2048;
constexpr int NH  = 16;   // query heads
constexpr int KHn = 8;    // kv heads
constexpr int HD  = 128;  // head dim
constexpr int FF  = 8192; // ffw dim
constexpr int Mtot = Bc * Tt;      // 4096
constexpr int GG  = NH / KHn;      // 2

// -------- scratch (static device globals; no allocations) --------
__device__ float g_xn  [(size_t)Mtot * Dd];
__device__ float g_q   [(size_t)Mtot * NH * HD];
__device__ float g_k   [(size_t)Mtot * KHn * HD];
__device__ float g_v   [(size_t)Mtot * KHn * HD];
__device__ float g_enc [(size_t)Mtot * NH * HD];
__device__ float g_res [(size_t)Mtot * Dd];
__device__ float g_h   [(size_t)Mtot * Dd];
__device__ float g_gate[(size_t)Mtot * FF];
// transposed + tf32-rounded weights, layout [N][K] K-major
constexpr size_t WQ_OFF  = 0;
constexpr size_t WKV_OFF = WQ_OFF  + (size_t)NH * Dd * HD;
constexpr size_t WAV_OFF = WKV_OFF + (size_t)2 * KHn * Dd * HD;
constexpr size_t WG_OFF  = WAV_OFF + (size_t)NH * HD * Dd;
constexpr size_t WL_OFF  = WG_OFF  + (size_t)2 * Dd * FF;
constexpr size_t WTOT    = WL_OFF  + (size_t)FF * Dd;
__device__ float g_w[WTOT];

__device__ __forceinline__ uint32_t f2tf32(float f) {
    uint32_t r;
    asm("cvt.rna.tf32.f32 %0, %1;" : "=r"(r) : "f"(f));
    return r;
}
__device__ __forceinline__ float roundtf32(float f) {
    return __uint_as_float(f2tf32(f));
}
__device__ __forceinline__ void cp_async16(uint32_t smem_addr, const void* gptr) {
    asm volatile("cp.async.cg.shared.global [%0], [%1], 16;" :: "r"(smem_addr), "l"(gptr));
}
__device__ __forceinline__ void mma_tf32(float& c0, float& c1, float& c2, float& c3,
                                         uint32_t a0, uint32_t a1, uint32_t a2, uint32_t a3,
                                         uint32_t b0, uint32_t b1) {
    asm volatile(
        "mma.sync.aligned.m16n8k8.row.col.f32.tf32.tf32.f32 "
        "{%0,%1,%2,%3}, {%4,%5,%6,%7}, {%8,%9}, {%0,%1,%2,%3};"
        : "+f"(c0), "+f"(c1), "+f"(c2), "+f"(c3)
        : "r"(a0), "r"(a1), "r"(a2), "r"(a3), "r"(b0), "r"(b1));
}

// ---------------- batched transpose + tf32 round: in[b][K][N] -> out[b][N][K]
__global__ void transpose_cvt_kernel(const float* __restrict__ src,
                                     float* __restrict__ dst, int K, int N) {
    __shared__ float tile[32][33];
    src += (size_t)blockIdx.z * K * N;
    dst += (size_t)blockIdx.z * K * N;
    int n0 = blockIdx.x * 32, k0 = blockIdx.y * 32;
    int tx = threadIdx.x, ty = threadIdx.y;  // 32 x 8
    #pragma unroll
    for (int i = 0; i < 32; i += 8)
        tile[ty + i][tx] = src[(size_t)(k0 + ty + i) * N + n0 + tx];
    __syncthreads();
    #pragma unroll
    for (int i = 0; i < 32; i += 8)
        dst[(size_t)(n0 + ty + i) * K + k0 + tx] = roundtf32(tile[tx][ty + i]);
}

// ---------------- RMSNorm (optionally tf32-rounded output) ----------------
__global__ void rmsnorm_kernel(const float* __restrict__ x,
                               const float* __restrict__ scale,
                               float* __restrict__ out, int roundOut) {
    int row = blockIdx.x;
    const float* xr = x + (size_t)row * Dd;
    float ss = 0.f;
    for (int i = threadIdx.x; i < Dd; i += blockDim.x) {
        float v = xr[i];
        ss += v * v;
    }
    __shared__ float red[32];
    #pragma unroll
    for (int o = 16; o; o >>= 1) ss += __shfl_xor_sync(0xffffffffu, ss, o);
    if ((threadIdx.x & 31) == 0) red[threadIdx.x >> 5] = ss;
    __syncthreads();
    if (threadIdx.x < 32) {
        float v = (threadIdx.x < (blockDim.x >> 5)) ? red[threadIdx.x] : 0.f;
        #pragma unroll
        for (int o = 16; o; o >>= 1) v += __shfl_xor_sync(0xffffffffu, v, o);
        if (threadIdx.x == 0) red[0] = v;
    }
    __syncthreads();
    float inv = rsqrtf(red[0] / (float)Dd + 1e-6f);
    float* outr = out + (size_t)row * Dd;
    for (int i = threadIdx.x; i < Dd; i += blockDim.x) {
        float v = xr[i] * inv * (1.f + scale[i]);
        outr[i] = roundOut ? roundtf32(v) : v;
    }
}

// ======= TF32 mma GEMM, warp tile 64x64 (1:1 LDS:HMMA) =======
// C[M,N] = A[M,Kd] @ Bt[N,Kd]^T. A row-major [M][K], Bt K-major [N][K].
// Tile 128x256x32, 256 threads = 8 warps (2x4), 3-stage cp.async pipeline.
constexpr int GM = 128, GN = 256, GK = 32;
constexpr int TSTR = GK + 4;   // 36 words: bank = 4*row + k (mod 32) -> conflict-free frags
constexpr int STG  = 3;
constexpr int AWORDS = GM * TSTR;   // per stage
constexpr int BWORDS = GN * TSTR;
constexpr int STGW   = AWORDS + BWORDS;
constexpr int GEMM_SMEM = STG * STGW * (int)sizeof(float);

extern __shared__ float dynsmem[];

__global__ __launch_bounds__(256, 1) void gemm_tc_kernel(
    const float* __restrict__ A, const float* __restrict__ Bt,
    const float* __restrict__ resid, const float* __restrict__ gelu_src,
    float* __restrict__ C, int Kd, int ldc, int roundOut) {

    float* smem = dynsmem;
    int m0 = blockIdx.y * GM, n0 = blockIdx.x * GN;
    int tid  = threadIdx.x;
    int lane = tid & 31, warp = tid >> 5;
    int grp = lane >> 2, tig = lane & 3;
    int wm = (warp >> 2) * 64;   // 0 / 64
    int wn = (warp & 3) * 64;    // 0,64,128,192

    float acc[4][8][4];
    #pragma unroll
    for (int mt = 0; mt < 4; mt++)
        #pragma unroll
        for (int nt = 0; nt < 8; nt++)
            #pragma unroll
            for (int r = 0; r < 4; r++) acc[mt][nt][r] = 0.f;

    int ntile = Kd / GK;

    // per-tile loads: A 128x32 fl = 1024 16B-chunks (4/thread), B 256x32 = 2048 (8/thread)
    auto issue_tile = [&](int t) {
        int s = t % STG;
        int k0 = t * GK;
        float* As = smem + (size_t)s * STGW;
        float* Bs = As + AWORDS;
        #pragma unroll
        for (int j = 0; j < 4; j++) {
            int c = tid + j * 256;
            int row = c >> 3, o = (c & 7) * 4;
            cp_async16((uint32_t)__cvta_generic_to_shared(&As[row * TSTR + o]),
                       &A[(size_t)(m0 + row) * Kd + k0 + o]);
        }
        #pragma unroll
        for (int j = 0; j < 8; j++) {
            int c = tid + j * 256;
            int row = c >> 3, o = (c & 7) * 4;
            cp_async16((uint32_t)__cvta_generic_to_shared(&Bs[row * TSTR + o]),
                       &Bt[(size_t)(n0 + row) * Kd + k0 + o]);
        }
    };

    issue_tile(0);
    asm volatile("cp.async.commit_group;");
    if (ntile > 1) issue_tile(1);
    asm volatile("cp.async.commit_group;");
    asm volatile("cp.async.wait_group 1;");
    __syncthreads();

    for (int t = 0; t < ntile; t++) {
        int s = t % STG;
        const uint32_t* As = (const uint32_t*)(smem + (size_t)s * STGW);
        const uint32_t* Bs = As + AWORDS;

        if (t + 2 < ntile) issue_tile(t + 2);
        asm volatile("cp.async.commit_group;");

        #pragma unroll
        for (int kk = 0; kk < 4; kk++) {
            int k = kk * 8;
            uint32_t af[4][4], bf[8][2];
            #pragma unroll
            for (int mt = 0; mt < 4; mt++) {
                int row = wm + mt * 16 + grp;
                af[mt][0] = As[(row    ) * TSTR + k + tig];
                af[mt][1] = As[(row + 8) * TSTR + k + tig];
                af[mt][2] = As[(row    ) * TSTR + k + tig + 4];
                af[mt][3] = As[(row + 8) * TSTR + k + tig + 4];
            }
            #pragma unroll
            for (int nt = 0; nt < 8; nt++) {
                int col = wn + nt * 8 + grp;
                bf[nt][0] = Bs[col * TSTR + k + tig];
                bf[nt][1] = Bs[col * TSTR + k + tig + 4];
            }
            #pragma unroll
            for (int mt = 0; mt < 4; mt++)
                #pragma unroll
                for (int nt = 0; nt < 8; nt++)
                    mma_tf32(acc[mt][nt][0], acc[mt][nt][1], acc[mt][nt][2], acc[mt][nt][3],
                             af[mt][0], af[mt][1], af[mt][2], af[mt][3],
                             bf[nt][0], bf[nt][1]);
        }

        asm volatile("cp.async.wait_group 1;");
        __syncthreads();
    }

    // epilogue: c0,c1 at (m,n),(m,n+1); c2,c3 at (m+8,n),(m+8,n+1)
    #pragma unroll
    for (int mt = 0; mt < 4; mt++) {
        #pragma unroll
        for (int nt = 0; nt < 8; nt++) {
            int m = m0 + wm + mt * 16 + grp;
            int n = n0 + wn + nt * 8 + 2 * tig;
            float2 v0 = make_float2(acc[mt][nt][0], acc[mt][nt][1]);
            float2 v1 = make_float2(acc[mt][nt][2], acc[mt][nt][3]);
            if (resid) {
                float2 r0 = *(const float2*)&resid[(size_t)m * ldc + n];
                float2 r1 = *(const float2*)&resid[(size_t)(m + 8) * ldc + n];
                v0.x += r0.x; v0.y += r0.y;
                v1.x += r1.x; v1.y += r1.y;
            }
            if (gelu_src) {
                float2 g0 = *(const float2*)&gelu_src[(size_t)m * ldc + n];
                float2 g1 = *(const float2*)&gelu_src[(size_t)(m + 8) * ldc + n];
                float t0 = tanhf(0.7978845608028654f * (g0.x + 0.044715f * g0.x * g0.x * g0.x));
                float t1 = tanhf(0.7978845608028654f * (g0.y + 0.044715f * g0.y * g0.y * g0.y));
                float t2 = tanhf(0.7978845608028654f * (g1.x + 0.044715f * g1.x * g1.x * g1.x));
                float t3 = tanhf(0.7978845608028654f * (g1.y + 0.044715f * g1.y * g1.y * g1.y));
                v0.x *= 0.5f * g0.x * (1.f + t0);
                v0.y *= 0.5f * g0.y * (1.f + t1);
                v1.x *= 0.5f * g1.x * (1.f + t2);
                v1.y *= 0.5f * g1.y * (1.f + t3);
            }
            if (roundOut) {
                v0.x = roundtf32(v0.x); v0.y = roundtf32(v0.y);
                v1.x = roundtf32(v1.x); v1.y = roundtf32(v1.y);
            }
            *(float2*)&C[(size_t)m * ldc + n]       = v0;
            *(float2*)&C[(size_t)(m + 8) * ldc + n] = v1;
        }
    }
}

// ---------------- RoPE (in place, tf32-rounded output) ----------------
__global__ void rope_kernel(float* __restrict__ x, const int* __restrict__ positions,
                            int heads, float outscale) {
    int row = blockIdx.x;
    int h   = blockIdx.y;
    int i   = threadIdx.x;  // 0..63
    float pos = (float)positions[row];
    float ts = powf(10000.f, (float)i / 64.f);
    float ang = pos / ts;
    float s, c;
    sincosf(ang, &s, &c);
    float* p = x + ((size_t)row * heads + h) * HD;
    float x1 = p[i], x2 = p[i + 64];
    p[i]      = roundtf32((x1 * c - x2 * s) * outscale);
    p[i + 64] = roundtf32((x2 * c + x1 * s) * outscale);
}

// ---------------- Flash attention (tf32 mma.sync, causal) -------------
constexpr int FBQ = 64, FBS = 64;
constexpr int KVSTR = HD + 8;   // 136
constexpr int PSTR  = FBS + 8;  // 72

__global__ __launch_bounds__(128, 1) void flash_tc_kernel(
    const float* __restrict__ q, const float* __restrict__ k,
    const float* __restrict__ v, float* __restrict__ enc) {

    int tq0 = blockIdx.x * FBQ;
    int n   = blockIdx.y;
    int b   = blockIdx.z;
    int kvh = n / GG;
    int tid  = threadIdx.x;
    int lane = tid & 31, warp = tid >> 5;
    int grp = lane >> 2, tig = lane & 3;
    int wq = warp * 16;

    float* Qs = dynsmem;
    float* Ks = Qs + FBQ * KVSTR;
    float* Vs = Ks + FBS * KVSTR;
    float* Ps = Vs + FBS * KVSTR;
    float* Pw = Ps + warp * 16 * PSTR;

    for (int i = tid; i < FBQ * (HD / 4); i += 128) {
        int row = i >> 5, c4 = (i & 31) * 4;
        float4 qv = *(const float4*)&q[(((size_t)b * Tt + tq0 + row) * NH + n) * HD + c4];
        *(float4*)&Qs[row * KVSTR + c4] = qv;
    }

    float m0v = -1e30f, m1v = -1e30f, l0 = 0.f, l1 = 0.f;
    float O[16][4];
    #pragma unroll
    for (int nt = 0; nt < 16; nt++)
        #pragma unroll
        for (int r = 0; r < 4; r++) O[nt][r] = 0.f;

    int ntiles = blockIdx.x + 1;
    for (int kt = 0; kt < ntiles; kt++) {
        int s0 = kt * FBS;
        __syncthreads();
        for (int i = tid; i < FBS * (HD / 4); i += 128) {
            int row = i >> 5, c4 = (i & 31) * 4;
            size_t g = (((size_t)b * Tt + s0 + row) * KHn + kvh) * HD + c4;
            *(float4*)&Ks[row * KVSTR + c4] = *(const float4*)&k[g];
            *(float4*)&Vs[row * KVSTR + c4] = *(const float4*)&v[g];
        }
        __syncthreads();

        float sc[8][4];
        #pragma unroll
        for (int nt = 0; nt < 8; nt++)
            #pragma unroll
            for (int r = 0; r < 4; r++) sc[nt][r] = 0.f;

        const uint32_t* QsU = (const uint32_t*)Qs;
        const uint32_t* KsU = (const uint32_t*)Ks;
        const uint32_t* VsU = (const uint32_t*)Vs;
        #pragma unroll
        for (int kk = 0; kk < 16; kk++) {
            int kd = kk * 8;
            uint32_t a0 = QsU[(wq + grp    ) * KVSTR + kd + tig];
            uint32_t a1 = QsU[(wq + grp + 8) * KVSTR + kd + tig];
            uint32_t a2 = QsU[(wq + grp    ) * KVSTR + kd + tig + 4];
            uint32_t a3 = QsU[(wq + grp + 8) * KVSTR + kd + tig + 4];
            #pragma unroll
            for (int nt = 0; nt < 8; nt++) {
                uint32_t b0 = KsU[(nt * 8 + grp) * KVSTR + kd + tig];
                uint32_t b1 = KsU[(nt * 8 + grp) * KVSTR + kd + tig + 4];
                mma_tf32(sc[nt][0], sc[nt][1], sc[nt][2], sc[nt][3],
                         a0, a1, a2, a3, b0, b1);
            }
        }

        int q0 = tq0 + wq + grp, q1 = q0 + 8;
        #pragma unroll
        for (int nt = 0; nt < 8; nt++) {
            int s = s0 + nt * 8 + 2 * tig;
            if (s     > q0) sc[nt][0] = -1e30f;
            if (s + 1 > q0) sc[nt][1] = -1e30f;
            if (s     > q1) sc[nt][2] = -1e30f;
            if (s + 1 > q1) sc[nt][3] = -1e30f;
        }

        float r0 = -1e30f, r1 = -1e30f;
        #pragma unroll
        for (int nt = 0; nt < 8; nt++) {
            r0 = fmaxf(r0, fmaxf(sc[nt][0], sc[nt][1]));
            r1 = fmaxf(r1, fmaxf(sc[nt][2], sc[nt][3]));
        }
        #pragma unroll
        for (int off = 1; off <= 2; off <<= 1) {
            r0 = fmaxf(r0, __shfl_xor_sync(0xffffffffu, r0, off));
            r1 = fmaxf(r1, __shfl_xor_sync(0xffffffffu, r1, off));
        }
        float mn0 = fmaxf(m0v, r0), mn1 = fmaxf(m1v, r1);
        float al0 = __expf(m0v - mn0), al1 = __expf(m1v - mn1);
        m0v = mn0; m1v = mn1;

        float rs0 = 0.f, rs1 = 0.f;
        #pragma unroll
        for (int nt = 0; nt < 8; nt++) {
            float p0 = __expf(sc[nt][0] - m0v);
            float p1 = __expf(sc[nt][1] - m0v);
            float p2 = __expf(sc[nt][2] - m1v);
            float p3 = __expf(sc[nt][3] - m1v);
            rs0 += p0 + p1; rs1 += p2 + p3;
            int cidx = nt * 8 + 2 * tig;
            Pw[(grp    ) * PSTR + cidx]     = roundtf32(p0);
            Pw[(grp    ) * PSTR + cidx + 1] = roundtf32(p1);
            Pw[(grp + 8) * PSTR + cidx]     = roundtf32(p2);
            Pw[(grp + 8) * PSTR + cidx + 1] = roundtf32(p3);
        }
        #pragma unroll
        for (int off = 1; off <= 2; off <<= 1) {
            rs0 += __shfl_xor_sync(0xffffffffu, rs0, off);
            rs1 += __shfl_xor_sync(0xffffffffu, rs1, off);
        }
        l0 = l0 * al0 + rs0;
        l1 = l1 * al1 + rs1;

        #pragma unroll
        for (int nt = 0; nt < 16; nt++) {
            O[nt][0] *= al0; O[nt][1] *= al0;
            O[nt][2] *= al1; O[nt][3] *= al1;
        }

        __syncwarp();
        const uint32_t* PwU = (const uint32_t*)Pw;
        #pragma unroll
        for (int kk = 0; kk < 8; kk++) {
            int ks = kk * 8;
            uint32_t a0 = PwU[(grp    ) * PSTR + ks + tig];
            uint32_t a1 = PwU[(grp + 8) * PSTR + ks + tig];
            uint32_t a2 = PwU[(grp    ) * PSTR + ks + tig + 4];
            uint32_t a3 = PwU[(grp + 8) * PSTR + ks + tig + 4];
            #pragma unroll
            for (int nt = 0; nt < 16; nt++) {
                uint32_t b0 = VsU[(ks + tig    ) * KVSTR + nt * 8 + grp];
                uint32_t b1 = VsU[(ks + tig + 4) * KVSTR + nt * 8 + grp];
                mma_tf32(O[nt][0], O[nt][1], O[nt][2], O[nt][3],
                         a0, a1, a2, a3, b0, b1);
            }
        }
    }

    float il0 = 1.f / l0, il1 = 1.f / l1;
    int qr0 = tq0 + wq + grp, qr1 = qr0 + 8;
    #pragma unroll
    for (int nt = 0; nt < 16; nt++) {
        int c = nt * 8 + 2 * tig;
        float* e0 = &g_enc[(((size_t)b * Tt + qr0) * NH + n) * HD + c];
        float* e1 = &g_enc[(((size_t)b * Tt + qr1) * NH + n) * HD + c];
        e0[0] = roundtf32(O[nt][0] * il0);
        e0[1] = roundtf32(O[nt][1] * il0);
        e1[0] = roundtf32(O[nt][2] * il1);
        e1[1] = roundtf32(O[nt][3] * il1);
    }
    (void)enc;
}

// ---------------- launch ----------------
extern "C" void kernel_launch(void* const* d_in, const int* in_sizes, int n_in,
                              void* d_out, int out_size) {
    const float* x        = (const float*)d_in[0];
    const int*   pos      = (const int*)  d_in[1];
    // d_in[2] attn_mask: causal, recomputed in-kernel
    const float* w_q      = (const float*)d_in[3];
    const float* w_kv     = (const float*)d_in[4];
    const float* w_av     = (const float*)d_in[5];
    const float* s_attn   = (const float*)d_in[6];
    const float* s_ffw    = (const float*)d_in[7];
    const float* w_gating = (const float*)d_in[8];
    const float* w_linear = (const float*)d_in[9];
    float* out = (float*)d_out;

    float *xn, *qp, *kp, *vp, *encp, *resp, *hp, *gatep, *wc;
    cudaGetSymbolAddress((void**)&xn,    g_xn);
    cudaGetSymbolAddress((void**)&qp,    g_q);
    cudaGetSymbolAddress((void**)&kp,    g_k);
    cudaGetSymbolAddress((void**)&vp,    g_v);
    cudaGetSymbolAddress((void**)&encp,  g_enc);
    cudaGetSymbolAddress((void**)&resp,  g_res);
    cudaGetSymbolAddress((void**)&hp,    g_h);
    cudaGetSymbolAddress((void**)&gatep, g_gate);
    cudaGetSymbolAddress((void**)&wc,    g_w);

    cudaFuncSetAttribute(gemm_tc_kernel, cudaFuncAttributeMaxDynamicSharedMemorySize, GEMM_SMEM);

    // 0. transpose + tf32-round weights to [N][K] K-major
    dim3 tb(32, 8);
    transpose_cvt_kernel<<<dim3(HD / 32, Dd / 32, NH),      tb>>>(w_q,      wc + WQ_OFF,  Dd, HD);
    transpose_cvt_kernel<<<dim3(HD / 32, Dd / 32, 2 * KHn), tb>>>(w_kv,     wc + WKV_OFF, Dd, HD);
    transpose_cvt_kernel<<<dim3(Dd / 32, (NH * HD) / 32, 1),tb>>>(w_av,     wc + WAV_OFF, NH * HD, Dd);
    transpose_cvt_kernel<<<dim3(FF / 32, Dd / 32, 2),       tb>>>(w_gating, wc + WG_OFF,  Dd, FF);
    transpose_cvt_kernel<<<dim3(Dd / 32, FF / 32, 1),       tb>>>(w_linear, wc + WL_OFF,  FF, Dd);

    // 1. pre-attn rmsnorm (tf32-rounded out)
    rmsnorm_kernel<<<Mtot, 256>>>(x, s_attn, xn, 1);

    // 2. projections (wide GEMMs; weight row n = head*HD + h matches q/k/v layout)
    gemm_tc_kernel<<<dim3((NH * HD) / GN, Mtot / GM), 256, GEMM_SMEM>>>(
        xn, wc + WQ_OFF, nullptr, nullptr, qp, Dd, NH * HD, 0);
    gemm_tc_kernel<<<dim3((KHn * HD) / GN, Mtot / GM), 256, GEMM_SMEM>>>(
        xn, wc + WKV_OFF, nullptr, nullptr, kp, Dd, KHn * HD, 0);
    gemm_tc_kernel<<<dim3((KHn * HD) / GN, Mtot / GM), 256, GEMM_SMEM>>>(
        xn, wc + WKV_OFF + (size_t)KHn * Dd * HD, nullptr, nullptr, vp, Dd, KHn * HD, 1);

    // 3. rope (outputs tf32-rounded)
    rope_kernel<<<dim3(Mtot, NH), 64>>>(qp, pos, NH, 0.08838834764831845f); // H^-0.5
    rope_kernel<<<dim3(Mtot, KHn), 64>>>(kp, pos, KHn, 1.f);

    // 4. flash attention
    int fa_smem = (FBQ * KVSTR + 2 * FBS * KVSTR + 4 * 16 * PSTR) * (int)sizeof(float);
    cudaFuncSetAttribute(flash_tc_kernel, cudaFuncAttributeMaxDynamicSharedMemorySize, fa_smem);
    flash_tc_kernel<<<dim3(Tt / FBQ, NH, Bc), 128, fa_smem>>>(qp, kp, vp, encp);

    // 5. attn output proj + residual
    gemm_tc_kernel<<<dim3(Dd / GN, Mtot / GM), 256, GEMM_SMEM>>>(
        encp, wc + WAV_OFF, x, nullptr, resp, NH * HD, Dd, 0);

    // 6. pre-ffw rmsnorm (tf32-rounded out)
    rmsnorm_kernel<<<Mtot, 256>>>(resp, s_ffw, hp, 1);

    // 7. gate GEMM, then up GEMM with fused gelu(gate)*up -> gatep (rounded)
    gemm_tc_kernel<<<dim3(FF / GN, Mtot / GM), 256, GEMM_SMEM>>>(
        hp, wc + WG_OFF, nullptr, nullptr, gatep, Dd, FF, 0);
    gemm_tc_kernel<<<dim3(FF / GN, Mtot / GM), 256, GEMM_SMEM>>>(
        hp, wc + WG_OFF + (size_t)Dd * FF, nullptr, gatep, gatep, Dd, FF, 1);

    // 8. down proj + residual -> out
    gemm_tc_kernel<<<dim3(Dd / GN, Mtot / GM), 256, GEMM_SMEM>>>(
        gatep, wc + WL_OFF, resp, nullptr, out, FF, Dd, 0);
}

// round 12
// speedup vs baseline: 1.7990x; 1.7990x over previous
#include <cuda_runtime.h>
#include <cuda_fp16.h>
#include <math.h>
#include <stdint.h>

// Problem constants
constexpr int Bc  = 2;
constexpr int Tt  = 2048;
constexpr int Dd  = 2048;
constexpr int NH  = 16;   // query heads
constexpr int KHn = 8;    // kv heads
constexpr int HD  = 128;  // head dim
constexpr int FF  = 8192; // ffw dim
constexpr int Mtot = Bc * Tt;      // 4096
constexpr int GG  = NH / KHn;      // 2

// -------- scratch (static device globals; no allocations) --------
__device__ __half g_xn  [(size_t)Mtot * Dd];
__device__ __half g_q   [(size_t)Mtot * NH * HD];
__device__ __half g_k   [(size_t)Mtot * KHn * HD];
__device__ __half g_v   [(size_t)Mtot * KHn * HD];
__device__ __half g_enc [(size_t)Mtot * NH * HD];
__device__ float  g_res [(size_t)Mtot * Dd];
__device__ __half g_h   [(size_t)Mtot * Dd];
__device__ __half g_gate[(size_t)Mtot * FF];
// transposed fp16 weights, layout [N][K] K-major
constexpr size_t WQ_OFF  = 0;
constexpr size_t WKV_OFF = WQ_OFF  + (size_t)NH * Dd * HD;
constexpr size_t WAV_OFF = WKV_OFF + (size_t)2 * KHn * Dd * HD;
constexpr size_t WG_OFF  = WAV_OFF + (size_t)NH * HD * Dd;
constexpr size_t WL_OFF  = WG_OFF  + (size_t)2 * Dd * FF;
constexpr size_t WTOT    = WL_OFF  + (size_t)FF * Dd;
__device__ __half g_w[WTOT];

__device__ __forceinline__ void cp_async16(uint32_t smem_addr, const void* gptr) {
    asm volatile("cp.async.cg.shared.global [%0], [%1], 16;" :: "r"(smem_addr), "l"(gptr));
}
__device__ __forceinline__ void mma_f16(float& c0, float& c1, float& c2, float& c3,
                                        uint32_t a0, uint32_t a1, uint32_t a2, uint32_t a3,
                                        uint32_t b0, uint32_t b1) {
    asm volatile(
        "mma.sync.aligned.m16n8k16.row.col.f32.f16.f16.f32 "
        "{%0,%1,%2,%3}, {%4,%5,%6,%7}, {%8,%9}, {%0,%1,%2,%3};"
        : "+f"(c0), "+f"(c1), "+f"(c2), "+f"(c3)
        : "r"(a0), "r"(a1), "r"(a2), "r"(a3), "r"(b0), "r"(b1));
}

// ---------------- batched transpose + fp16: in[b][K][N] f32 -> out[b][N][K] f16
__global__ void transpose_cvt_kernel(const float* __restrict__ src,
                                     __half* __restrict__ dst, int K, int N) {
    __shared__ float tile[32][33];
    src += (size_t)blockIdx.z * K * N;
    dst += (size_t)blockIdx.z * K * N;
    int n0 = blockIdx.x * 32, k0 = blockIdx.y * 32;
    int tx = threadIdx.x, ty = threadIdx.y;  // 32 x 8
    #pragma unroll
    for (int i = 0; i < 32; i += 8)
        tile[ty + i][tx] = src[(size_t)(k0 + ty + i) * N + n0 + tx];
    __syncthreads();
    #pragma unroll
    for (int i = 0; i < 32; i += 8)
        dst[(size_t)(n0 + ty + i) * K + k0 + tx] = __float2half(tile[tx][ty + i]);
}

// ---------------- RMSNorm: float in -> half out ----------------
__global__ void rmsnorm_kernel(const float* __restrict__ x,
                               const float* __restrict__ scale,
                               __half* __restrict__ out) {
    int row = blockIdx.x;
    const float* xr = x + (size_t)row * Dd;
    float ss = 0.f;
    for (int i = threadIdx.x; i < Dd; i += blockDim.x) {
        float v = xr[i];
        ss += v * v;
    }
    __shared__ float red[32];
    #pragma unroll
    for (int o = 16; o; o >>= 1) ss += __shfl_xor_sync(0xffffffffu, ss, o);
    if ((threadIdx.x & 31) == 0) red[threadIdx.x >> 5] = ss;
    __syncthreads();
    if (threadIdx.x < 32) {
        float v = (threadIdx.x < (blockDim.x >> 5)) ? red[threadIdx.x] : 0.f;
        #pragma unroll
        for (int o = 16; o; o >>= 1) v += __shfl_xor_sync(0xffffffffu, v, o);
        if (threadIdx.x == 0) red[0] = v;
    }
    __syncthreads();
    float inv = rsqrtf(red[0] / (float)Dd + 1e-6f);
    __half* outr = out + (size_t)row * Dd;
    for (int i = threadIdx.x; i < Dd; i += blockDim.x)
        outr[i] = __float2half(xr[i] * inv * (1.f + scale[i]));
}

// ======= FP16 mma GEMM: C = A[M,Kd] @ Bt[N,Kd]^T =======
// Tile 128x128x32(halfs), 8 warps (2x4), warp tile 64x32, 3-stage cp.async.
constexpr int GM = 128, GN = 128, GK = 32;
constexpr int TSTRH = 40;              // halfs per row (20 words; 20*grp+tig distinct banks)
constexpr int STG  = 3;
constexpr int AHALF = GM * TSTRH;      // per stage (halfs)
constexpr int BHALF = GN * TSTRH;
constexpr int STGH  = AHALF + BHALF;
constexpr int GEMM_SMEM = STG * STGH * 2;

extern __shared__ __half dynsmem_h[];

// FOUT=1: float C (+resid). FOUT=0: half C (+optional gelu-gate multiply).
template <int FOUT>
__global__ __launch_bounds__(256, 2) void gemm_f16_kernel(
    const __half* __restrict__ A, const __half* __restrict__ Bt,
    const float* __restrict__ resid, const __half* __restrict__ gelu_src,
    void* __restrict__ Cv, int Kd, int ldc) {

    __half* smem = dynsmem_h;
    int m0 = blockIdx.y * GM, n0 = blockIdx.x * GN;
    int tid  = threadIdx.x;
    int lane = tid & 31, warp = tid >> 5;
    int grp = lane >> 2, tig = lane & 3;
    int wm = (warp >> 2) * 64;
    int wn = (warp & 3) * 32;

    float acc[4][4][4];
    #pragma unroll
    for (int mt = 0; mt < 4; mt++)
        #pragma unroll
        for (int nt = 0; nt < 4; nt++)
            #pragma unroll
            for (int r = 0; r < 4; r++) acc[mt][nt][r] = 0.f;

    int ntile = Kd / GK;

    // A tile 128x64B = 512 chunks, B same: 2 chunks each per thread
    auto issue_tile = [&](int t) {
        int s = t % STG;
        int k0 = t * GK;
        __half* As = smem + (size_t)s * STGH;
        __half* Bs = As + AHALF;
        #pragma unroll
        for (int j = 0; j < 2; j++) {
            int c = tid + j * 256;
            int row = c >> 2, o8 = (c & 3) * 8;
            cp_async16((uint32_t)__cvta_generic_to_shared(&As[row * TSTRH + o8]),
                       &A[(size_t)(m0 + row) * Kd + k0 + o8]);
        }
        #pragma unroll
        for (int j = 0; j < 2; j++) {
            int c = tid + j * 256;
            int row = c >> 2, o8 = (c & 3) * 8;
            cp_async16((uint32_t)__cvta_generic_to_shared(&Bs[row * TSTRH + o8]),
                       &Bt[(size_t)(n0 + row) * Kd + k0 + o8]);
        }
    };

    issue_tile(0);
    asm volatile("cp.async.commit_group;");
    if (ntile > 1) issue_tile(1);
    asm volatile("cp.async.commit_group;");
    asm volatile("cp.async.wait_group 1;");
    __syncthreads();

    for (int t = 0; t < ntile; t++) {
        int s = t % STG;
        const uint32_t* As = (const uint32_t*)(smem + (size_t)s * STGH);
        const uint32_t* Bs = As + AHALF / 2;

        if (t + 2 < ntile) issue_tile(t + 2);
        asm volatile("cp.async.commit_group;");

        #pragma unroll
        for (int kk = 0; kk < 2; kk++) {     // 2 x K=16 per 32-half tile
            int kw = kk * 8;                  // word offset
            uint32_t af[4][4], bf[4][2];
            #pragma unroll
            for (int mt = 0; mt < 4; mt++) {
                int row = wm + mt * 16 + grp;
                af[mt][0] = As[row * 20 + kw + tig];
                af[mt][1] = As[(row + 8) * 20 + kw + tig];
                af[mt][2] = As[row * 20 + kw + tig + 4];
                af[mt][3] = As[(row + 8) * 20 + kw + tig + 4];
            }
            #pragma unroll
            for (int nt = 0; nt < 4; nt++) {
                int col = wn + nt * 8 + grp;
                bf[nt][0] = Bs[col * 20 + kw + tig];
                bf[nt][1] = Bs[col * 20 + kw + tig + 4];
            }
            #pragma unroll
            for (int mt = 0; mt < 4; mt++)
                #pragma unroll
                for (int nt = 0; nt < 4; nt++)
                    mma_f16(acc[mt][nt][0], acc[mt][nt][1], acc[mt][nt][2], acc[mt][nt][3],
                            af[mt][0], af[mt][1], af[mt][2], af[mt][3],
                            bf[nt][0], bf[nt][1]);
        }

        asm volatile("cp.async.wait_group 1;");
        __syncthreads();
    }

    // epilogue: c0,c1 at (m,n),(m,n+1); c2,c3 at (m+8,n),(m+8,n+1)
    #pragma unroll
    for (int mt = 0; mt < 4; mt++) {
        #pragma unroll
        for (int nt = 0; nt < 4; nt++) {
            int m = m0 + wm + mt * 16 + grp;
            int n = n0 + wn + nt * 8 + 2 * tig;
            float v00 = acc[mt][nt][0], v01 = acc[mt][nt][1];
            float v10 = acc[mt][nt][2], v11 = acc[mt][nt][3];
            if (FOUT) {
                float* C = (float*)Cv;
                if (resid) {
                    float2 r0 = *(const float2*)&resid[(size_t)m * ldc + n];
                    float2 r1 = *(const float2*)&resid[(size_t)(m + 8) * ldc + n];
                    v00 += r0.x; v01 += r0.y; v10 += r1.x; v11 += r1.y;
                }
                *(float2*)&C[(size_t)m * ldc + n]       = make_float2(v00, v01);
                *(float2*)&C[(size_t)(m + 8) * ldc + n] = make_float2(v10, v11);
            } else {
                __half* C = (__half*)Cv;
                if (gelu_src) {
                    __half2 h0 = *(const __half2*)&gelu_src[(size_t)m * ldc + n];
                    __half2 h1 = *(const __half2*)&gelu_src[(size_t)(m + 8) * ldc + n];
                    float g0 = __half2float(h0.x), g1 = __half2float(h0.y);
                    float g2 = __half2float(h1.x), g3 = __half2float(h1.y);
                    float t0 = tanhf(0.7978845608028654f * (g0 + 0.044715f * g0 * g0 * g0));
                    float t1 = tanhf(0.7978845608028654f * (g1 + 0.044715f * g1 * g1 * g1));
                    float t2 = tanhf(0.7978845608028654f * (g2 + 0.044715f * g2 * g2 * g2));
                    float t3 = tanhf(0.7978845608028654f * (g3 + 0.044715f * g3 * g3 * g3));
                    v00 *= 0.5f * g0 * (1.f + t0);
                    v01 *= 0.5f * g1 * (1.f + t1);
                    v10 *= 0.5f * g2 * (1.f + t2);
                    v11 *= 0.5f * g3 * (1.f + t3);
                }
                *(__half2*)&C[(size_t)m * ldc + n] =
                    __floats2half2_rn(v00, v01);
                *(__half2*)&C[(size_t)(m + 8) * ldc + n] =
                    __floats2half2_rn(v10, v11);
            }
        }
    }
}

// ---------------- RoPE (in place on half) ----------------
__global__ void rope_kernel(__half* __restrict__ x, const int* __restrict__ positions,
                            int heads, float outscale) {
    int row = blockIdx.x;
    int h   = blockIdx.y;
    int i   = threadIdx.x;  // 0..63
    float pos = (float)positions[row];
    float ts = powf(10000.f, (float)i / 64.f);
    float ang = pos / ts;
    float s, c;
    sincosf(ang, &s, &c);
    __half* p = x + ((size_t)row * heads + h) * HD;
    float x1 = __half2float(p[i]), x2 = __half2float(p[i + 64]);
    p[i]      = __float2half((x1 * c - x2 * s) * outscale);
    p[i + 64] = __float2half((x2 * c + x1 * s) * outscale);
}

// ---------------- Flash attention (fp16 mma, causal) -------------
constexpr int FBQ = 64, FBS = 64;
constexpr int QKSTR = HD + 8;    // 136 halfs (68 words, ≡4 mod 32)
constexpr int VTSTR = FBS + 8;   // 72 halfs (36 words)
constexpr int PSTRH = FBS + 8;   // 72 halfs

__global__ __launch_bounds__(128, 2) void flash_f16_kernel(
    const __half* __restrict__ q, const __half* __restrict__ k,
    const __half* __restrict__ v) {

    int tq0 = blockIdx.x * FBQ;
    int n   = blockIdx.y;
    int b   = blockIdx.z;
    int kvh = n / GG;
    int tid  = threadIdx.x;
    int lane = tid & 31, warp = tid >> 5;
    int grp = lane >> 2, tig = lane & 3;
    int wq = warp * 16;

    __half* Qs = dynsmem_h;                 // [FBQ][QKSTR]
    __half* Ks = Qs + FBQ * QKSTR;          // [FBS][QKSTR]
    __half* Vt = Ks + FBS * QKSTR;          // [HD][VTSTR] (d-major)
    __half* Ps = Vt + HD * VTSTR;           // [4][16][PSTRH]
    __half* Pw = Ps + warp * 16 * PSTRH;

    // load Q tile: 64 rows x 256B = 1024 16B-chunks, 8/thread
    #pragma unroll
    for (int j = 0; j < 8; j++) {
        int c = tid + j * 128;
        int row = c >> 4, o8 = (c & 15) * 8;
        cp_async16((uint32_t)__cvta_generic_to_shared(&Qs[row * QKSTR + o8]),
                   &q[(((size_t)b * Tt + tq0 + row) * NH + n) * HD + o8]);
    }
    asm volatile("cp.async.commit_group;");

    float m0v = -1e30f, m1v = -1e30f, l0 = 0.f, l1 = 0.f;
    float O[16][4];
    #pragma unroll
    for (int nt = 0; nt < 16; nt++)
        #pragma unroll
        for (int r = 0; r < 4; r++) O[nt][r] = 0.f;

    int ntiles = blockIdx.x + 1;
    for (int kt = 0; kt < ntiles; kt++) {
        int s0 = kt * FBS;
        __syncthreads();
        // K: 64 rows x 128 halfs = 1024 16B-chunks, 8/thread
        #pragma unroll
        for (int j = 0; j < 8; j++) {
            int c = tid + j * 128;
            int row = c >> 4, o8 = (c & 15) * 8;
            cp_async16((uint32_t)__cvta_generic_to_shared(&Ks[row * QKSTR + o8]),
                       &k[(((size_t)b * Tt + s0 + row) * KHn + kvh) * HD + o8]);
        }
        asm volatile("cp.async.commit_group;");
        // V transposed into Vt[d][s] (plain ld/st)
        #pragma unroll
        for (int j = 0; j < 8; j++) {
            int c = tid + j * 128;
            int s = c >> 4, d0 = (c & 15) * 8;
            uint4 raw = *(const uint4*)&v[(((size_t)b * Tt + s0 + s) * KHn + kvh) * HD + d0];
            __half hv[8];
            *(uint4*)hv = raw;
            #pragma unroll
            for (int i = 0; i < 8; i++)
                Vt[(d0 + i) * VTSTR + s] = hv[i];
        }
        asm volatile("cp.async.wait_group 0;");
        __syncthreads();

        // ---- S = Q K^T
        float sc[8][4];
        #pragma unroll
        for (int nt = 0; nt < 8; nt++)
            #pragma unroll
            for (int r = 0; r < 4; r++) sc[nt][r] = 0.f;

        const uint32_t* QsU = (const uint32_t*)Qs;
        const uint32_t* KsU = (const uint32_t*)Ks;
        const uint32_t* VtU = (const uint32_t*)Vt;
        #pragma unroll
        for (int kk = 0; kk < 8; kk++) {     // HD/16
            int kw = kk * 8;
            uint32_t a0 = QsU[(wq + grp) * 68 + kw + tig];
            uint32_t a1 = QsU[(wq + grp + 8) * 68 + kw + tig];
            uint32_t a2 = QsU[(wq + grp) * 68 + kw + tig + 4];
            uint32_t a3 = QsU[(wq + grp + 8) * 68 + kw + tig + 4];
            #pragma unroll
            for (int nt = 0; nt < 8; nt++) {
                uint32_t b0 = KsU[(nt * 8 + grp) * 68 + kw + tig];
                uint32_t b1 = KsU[(nt * 8 + grp) * 68 + kw + tig + 4];
                mma_f16(sc[nt][0], sc[nt][1], sc[nt][2], sc[nt][3],
                        a0, a1, a2, a3, b0, b1);
            }
        }

        int q0 = tq0 + wq + grp, q1 = q0 + 8;
        #pragma unroll
        for (int nt = 0; nt < 8; nt++) {
            int s = s0 + nt * 8 + 2 * tig;
            if (s     > q0) sc[nt][0] = -1e30f;
            if (s + 1 > q0) sc[nt][1] = -1e30f;
            if (s     > q1) sc[nt][2] = -1e30f;
            if (s + 1 > q1) sc[nt][3] = -1e30f;
        }

        float r0 = -1e30f, r1 = -1e30f;
        #pragma unroll
        for (int nt = 0; nt < 8; nt++) {
            r0 = fmaxf(r0, fmaxf(sc[nt][0], sc[nt][1]));
            r1 = fmaxf(r1, fmaxf(sc[nt][2], sc[nt][3]));
        }
        #pragma unroll
        for (int off = 1; off <= 2; off <<= 1) {
            r0 = fmaxf(r0, __shfl_xor_sync(0xffffffffu, r0, off));
            r1 = fmaxf(r1, __shfl_xor_sync(0xffffffffu, r1, off));
        }
        float mn0 = fmaxf(m0v, r0), mn1 = fmaxf(m1v, r1);
        float al0 = __expf(m0v - mn0), al1 = __expf(m1v - mn1);
        m0v = mn0; m1v = mn1;

        float rs0 = 0.f, rs1 = 0.f;
        uint32_t* PwU = (uint32_t*)Pw;
        #pragma unroll
        for (int nt = 0; nt < 8; nt++) {
            float p0 = __expf(sc[nt][0] - m0v);
            float p1 = __expf(sc[nt][1] - m0v);
            float p2 = __expf(sc[nt][2] - m1v);
            float p3 = __expf(sc[nt][3] - m1v);
            rs0 += p0 + p1; rs1 += p2 + p3;
            __half2 h0 = __floats2half2_rn(p0, p1);
            __half2 h1 = __floats2half2_rn(p2, p3);
            PwU[grp * 36 + nt * 4 + tig]       = *(uint32_t*)&h0;
            PwU[(grp + 8) * 36 + nt * 4 + tig] = *(uint32_t*)&h1;
        }
        #pragma unroll
        for (int off = 1; off <= 2; off <<= 1) {
            rs0 += __shfl_xor_sync(0xffffffffu, rs0, off);
            rs1 += __shfl_xor_sync(0xffffffffu, rs1, off);
        }
        l0 = l0 * al0 + rs0;
        l1 = l1 * al1 + rs1;

        #pragma unroll
        for (int nt = 0; nt < 16; nt++) {
            O[nt][0] *= al0; O[nt][1] *= al0;
            O[nt][2] *= al1; O[nt][3] *= al1;
        }

        __syncwarp();
        // ---- O += P V
        #pragma unroll
        for (int kk = 0; kk < 4; kk++) {     // FBS/16
            int kw = kk * 8;
            uint32_t a0 = PwU[grp * 36 + kw + tig];
            uint32_t a1 = PwU[(grp + 8) * 36 + kw + tig];
            uint32_t a2 = PwU[grp * 36 + kw + tig + 4];
            uint32_t a3 = PwU[(grp + 8) * 36 + kw + tig + 4];
            #pragma unroll
            for (int nt = 0; nt < 16; nt++) {
                uint32_t b0 = VtU[(nt * 8 + grp) * 36 + kw + tig];
                uint32_t b1 = VtU[(nt * 8 + grp) * 36 + kw + tig + 4];
                mma_f16(O[nt][0], O[nt][1], O[nt][2], O[nt][3],
                        a0, a1, a2, a3, b0, b1);
            }
        }
    }

    float il0 = 1.f / l0, il1 = 1.f / l1;
    int qr0 = tq0 + wq + grp, qr1 = qr0 + 8;
    #pragma unroll
    for (int nt = 0; nt < 16; nt++) {
        int c = nt * 8 + 2 * tig;
        *(__half2*)&g_enc[(((size_t)b * Tt + qr0) * NH + n) * HD + c] =
            __floats2half2_rn(O[nt][0] * il0, O[nt][1] * il0);
        *(__half2*)&g_enc[(((size_t)b * Tt + qr1) * NH + n) * HD + c] =
            __floats2half2_rn(O[nt][2] * il1, O[nt][3] * il1);
    }
}

// ---------------- launch ----------------
extern "C" void kernel_launch(void* const* d_in, const int* in_sizes, int n_in,
                              void* d_out, int out_size) {
    const float* x        = (const float*)d_in[0];
    const int*   pos      = (const int*)  d_in[1];
    // d_in[2] attn_mask: causal, recomputed in-kernel
    const float* w_q      = (const float*)d_in[3];
    const float* w_kv     = (const float*)d_in[4];
    const float* w_av     = (const float*)d_in[5];
    const float* s_attn   = (const float*)d_in[6];
    const float* s_ffw    = (const float*)d_in[7];
    const float* w_gating = (const float*)d_in[8];
    const float* w_linear = (const float*)d_in[9];
    float* out = (float*)d_out;

    __half *xn, *qp, *kp, *vp, *encp, *hp, *gatep, *wc;
    float *resp;
    cudaGetSymbolAddress((void**)&xn,    g_xn);
    cudaGetSymbolAddress((void**)&qp,    g_q);
    cudaGetSymbolAddress((void**)&kp,    g_k);
    cudaGetSymbolAddress((void**)&vp,    g_v);
    cudaGetSymbolAddress((void**)&encp,  g_enc);
    cudaGetSymbolAddress((void**)&resp,  g_res);
    cudaGetSymbolAddress((void**)&hp,    g_h);
    cudaGetSymbolAddress((void**)&gatep, g_gate);
    cudaGetSymbolAddress((void**)&wc,    g_w);

    cudaFuncSetAttribute(gemm_f16_kernel<0>, cudaFuncAttributeMaxDynamicSharedMemorySize, GEMM_SMEM);
    cudaFuncSetAttribute(gemm_f16_kernel<1>, cudaFuncAttributeMaxDynamicSharedMemorySize, GEMM_SMEM);

    // 0. transpose + fp16 weights to [N][K]
    dim3 tb(32, 8);
    transpose_cvt_kernel<<<dim3(HD / 32, Dd / 32, NH),      tb>>>(w_q,      wc + WQ_OFF,  Dd, HD);
    transpose_cvt_kernel<<<dim3(HD / 32, Dd / 32, 2 * KHn), tb>>>(w_kv,     wc + WKV_OFF, Dd, HD);
    transpose_cvt_kernel<<<dim3(Dd / 32, (NH * HD) / 32, 1),tb>>>(w_av,     wc + WAV_OFF, NH * HD, Dd);
    transpose_cvt_kernel<<<dim3(FF / 32, Dd / 32, 2),       tb>>>(w_gating, wc + WG_OFF,  Dd, FF);
    transpose_cvt_kernel<<<dim3(Dd / 32, FF / 32, 1),       tb>>>(w_linear, wc + WL_OFF,  FF, Dd);

    // 1. pre-attn rmsnorm -> half
    rmsnorm_kernel<<<Mtot, 256>>>(x, s_attn, xn);

    // 2. projections (half in/out)
    gemm_f16_kernel<0><<<dim3((NH * HD) / GN, Mtot / GM), 256, GEMM_SMEM>>>(
        xn, wc + WQ_OFF, nullptr, nullptr, qp, Dd, NH * HD);
    gemm_f16_kernel<0><<<dim3((KHn * HD) / GN, Mtot / GM), 256, GEMM_SMEM>>>(
        xn, wc + WKV_OFF, nullptr, nullptr, kp, Dd, KHn * HD);
    gemm_f16_kernel<0><<<dim3((KHn * HD) / GN, Mtot / GM), 256, GEMM_SMEM>>>(
        xn, wc + WKV_OFF + (size_t)KHn * Dd * HD, nullptr, nullptr, vp, Dd, KHn * HD);

    // 3. rope
    rope_kernel<<<dim3(Mtot, NH), 64>>>(qp, pos, NH, 0.08838834764831845f); // H^-0.5
    rope_kernel<<<dim3(Mtot, KHn), 64>>>(kp, pos, KHn, 1.f);

    // 4. flash attention (half everywhere, fp32 softmax/accum)
    int fa_smem = (FBQ * QKSTR + FBS * QKSTR + HD * VTSTR + 4 * 16 * PSTRH) * 2;
    cudaFuncSetAttribute(flash_f16_kernel, cudaFuncAttributeMaxDynamicSharedMemorySize, fa_smem);
    flash_f16_kernel<<<dim3(Tt / FBQ, NH, Bc), 128, fa_smem>>>(qp, kp, vp);

    // 5. attn output proj + residual (float out)
    gemm_f16_kernel<1><<<dim3(Dd / GN, Mtot / GM), 256, GEMM_SMEM>>>(
        encp, wc + WAV_OFF, x, nullptr, resp, NH * HD, Dd);

    // 6. pre-ffw rmsnorm -> half
    rmsnorm_kernel<<<Mtot, 256>>>(resp, s_ffw, hp);

    // 7. gate GEMM, then up GEMM with fused gelu(gate)*up -> gatep (in place)
    gemm_f16_kernel<0><<<dim3(FF / GN, Mtot / GM), 256, GEMM_SMEM>>>(
        hp, wc + WG_OFF, nullptr, nullptr, gatep, Dd, FF);
    gemm_f16_kernel<0><<<dim3(FF / GN, Mtot / GM), 256, GEMM_SMEM>>>(
        hp, wc + WG_OFF + (size_t)Dd * FF, nullptr, gatep, gatep, Dd, FF);

    // 8. down proj + residual -> out (float)
    gemm_f16_kernel<1><<<dim3(Dd / GN, Mtot / GM), 256, GEMM_SMEM>>>(
        gatep, wc + WL_OFF, resp, nullptr, out, FF, Dd);
}

// round 13
// speedup vs baseline: 2.0422x; 1.1352x over previous
#include <cuda_runtime.h>
#include <cuda_fp16.h>
#include <math.h>
#include <stdint.h>

// Problem constants
constexpr int Bc  = 2;
constexpr int Tt  = 2048;
constexpr int Dd  = 2048;
constexpr int NH  = 16;   // query heads
constexpr int KHn = 8;    // kv heads
constexpr int HD  = 128;  // head dim
constexpr int FF  = 8192; // ffw dim
constexpr int Mtot = Bc * Tt;      // 4096
constexpr int GG  = NH / KHn;      // 2

// -------- scratch (static device globals; no allocations) --------
__device__ __half g_xn  [(size_t)Mtot * Dd];
__device__ __half g_q   [(size_t)Mtot * NH * HD];
__device__ __half g_k   [(size_t)Mtot * KHn * HD];
__device__ __half g_v   [(size_t)Mtot * KHn * HD];
__device__ __half g_enc [(size_t)Mtot * NH * HD];
__device__ float  g_res [(size_t)Mtot * Dd];
__device__ __half g_h   [(size_t)Mtot * Dd];
__device__ __half g_gate[(size_t)Mtot * FF];
// transposed fp16 weights, layout [N][K] K-major
constexpr size_t WQ_OFF  = 0;
constexpr size_t WKV_OFF = WQ_OFF  + (size_t)NH * Dd * HD;
constexpr size_t WAV_OFF = WKV_OFF + (size_t)2 * KHn * Dd * HD;
constexpr size_t WG_OFF  = WAV_OFF + (size_t)NH * HD * Dd;
constexpr size_t WL_OFF  = WG_OFF  + (size_t)2 * Dd * FF;
constexpr size_t WTOT    = WL_OFF  + (size_t)FF * Dd;
__device__ __half g_w[WTOT];

__device__ __forceinline__ void cp_async16(uint32_t smem_addr, const void* gptr) {
    asm volatile("cp.async.cg.shared.global [%0], [%1], 16;" :: "r"(smem_addr), "l"(gptr));
}
__device__ __forceinline__ void mma_f16(float& c0, float& c1, float& c2, float& c3,
                                        uint32_t a0, uint32_t a1, uint32_t a2, uint32_t a3,
                                        uint32_t b0, uint32_t b1) {
    asm volatile(
        "mma.sync.aligned.m16n8k16.row.col.f32.f16.f16.f32 "
        "{%0,%1,%2,%3}, {%4,%5,%6,%7}, {%8,%9}, {%0,%1,%2,%3};"
        : "+f"(c0), "+f"(c1), "+f"(c2), "+f"(c3)
        : "r"(a0), "r"(a1), "r"(a2), "r"(a3), "r"(b0), "r"(b1));
}
__device__ __forceinline__ void ldsm_x4(uint32_t& r0, uint32_t& r1, uint32_t& r2, uint32_t& r3,
                                        uint32_t addr) {
    asm volatile("ldmatrix.sync.aligned.m8n8.x4.shared.b16 {%0,%1,%2,%3}, [%4];"
                 : "=r"(r0), "=r"(r1), "=r"(r2), "=r"(r3) : "r"(addr));
}

// ---------------- batched transpose + fp16: in[b][K][N] f32 -> out[b][N][K] f16
__global__ void transpose_cvt_kernel(const float* __restrict__ src,
                                     __half* __restrict__ dst, int K, int N) {
    __shared__ float tile[32][33];
    src += (size_t)blockIdx.z * K * N;
    dst += (size_t)blockIdx.z * K * N;
    int n0 = blockIdx.x * 32, k0 = blockIdx.y * 32;
    int tx = threadIdx.x, ty = threadIdx.y;  // 32 x 8
    #pragma unroll
    for (int i = 0; i < 32; i += 8)
        tile[ty + i][tx] = src[(size_t)(k0 + ty + i) * N + n0 + tx];
    __syncthreads();
    #pragma unroll
    for (int i = 0; i < 32; i += 8)
        dst[(size_t)(n0 + ty + i) * K + k0 + tx] = __float2half(tile[tx][ty + i]);
}

// ---------------- RMSNorm: float in -> half out ----------------
__global__ void rmsnorm_kernel(const float* __restrict__ x,
                               const float* __restrict__ scale,
                               __half* __restrict__ out) {
    int row = blockIdx.x;
    const float* xr = x + (size_t)row * Dd;
    float ss = 0.f;
    for (int i = threadIdx.x; i < Dd; i += blockDim.x) {
        float v = xr[i];
        ss += v * v;
    }
    __shared__ float red[32];
    #pragma unroll
    for (int o = 16; o; o >>= 1) ss += __shfl_xor_sync(0xffffffffu, ss, o);
    if ((threadIdx.x & 31) == 0) red[threadIdx.x >> 5] = ss;
    __syncthreads();
    if (threadIdx.x < 32) {
        float v = (threadIdx.x < (blockDim.x >> 5)) ? red[threadIdx.x] : 0.f;
        #pragma unroll
        for (int o = 16; o; o >>= 1) v += __shfl_xor_sync(0xffffffffu, v, o);
        if (threadIdx.x == 0) red[0] = v;
    }
    __syncthreads();
    float inv = rsqrtf(red[0] / (float)Dd + 1e-6f);
    __half* outr = out + (size_t)row * Dd;
    for (int i = threadIdx.x; i < Dd; i += blockDim.x)
        outr[i] = __float2half(xr[i] * inv * (1.f + scale[i]));
}

// ======= FP16 mma GEMM: C = A[M,Kd] @ Bt[N,Kd]^T (ldmatrix fragments) =======
constexpr int GM = 128, GN = 128, GK = 32;
constexpr int TSTRH = 40;              // halfs/row (80B: 8-row LDSM phases distinct)
constexpr int STG  = 3;
constexpr int AHALF = GM * TSTRH;
constexpr int BHALF = GN * TSTRH;
constexpr int STGH  = AHALF + BHALF;
constexpr int GEMM_SMEM = STG * STGH * 2;

extern __shared__ __half dynsmem_h[];

// FOUT=1: float C (+resid). FOUT=0: half C (+optional gelu-gate multiply).
template <int FOUT>
__global__ __launch_bounds__(256, 2) void gemm_f16_kernel(
    const __half* __restrict__ A, const __half* __restrict__ Bt,
    const float* __restrict__ resid, const __half* __restrict__ gelu_src,
    void* __restrict__ Cv, int Kd, int ldc) {

    __half* smem = dynsmem_h;
    uint32_t smb = (uint32_t)__cvta_generic_to_shared(dynsmem_h);
    int m0 = blockIdx.y * GM, n0 = blockIdx.x * GN;
    int tid  = threadIdx.x;
    int lane = tid & 31, warp = tid >> 5;
    int grp = lane >> 2, tig = lane & 3;
    int wm = (warp >> 2) * 64;
    int wn = (warp & 3) * 32;

    // ldmatrix per-lane address components
    int arow_l = (lane & 7) + ((lane >> 3) & 1) * 8;  // A: groups 0/1 rows, 2/3 k+8
    int acol_l = (lane >> 4) * 8;
    int brow_l = (lane & 7) + (lane >> 4) * 8;        // B: groups 0/1 k, 2/3 rows+8
    int bcol_l = ((lane >> 3) & 1) * 8;

    float acc[4][4][4];
    #pragma unroll
    for (int mt = 0; mt < 4; mt++)
        #pragma unroll
        for (int nt = 0; nt < 4; nt++)
            #pragma unroll
            for (int r = 0; r < 4; r++) acc[mt][nt][r] = 0.f;

    int ntile = Kd / GK;

    auto issue_tile = [&](int t) {
        int s = t % STG;
        int k0 = t * GK;
        __half* As = smem + (size_t)s * STGH;
        __half* Bs = As + AHALF;
        #pragma unroll
        for (int j = 0; j < 2; j++) {
            int c = tid + j * 256;
            int row = c >> 2, o8 = (c & 3) * 8;
            cp_async16((uint32_t)__cvta_generic_to_shared(&As[row * TSTRH + o8]),
                       &A[(size_t)(m0 + row) * Kd + k0 + o8]);
        }
        #pragma unroll
        for (int j = 0; j < 2; j++) {
            int c = tid + j * 256;
            int row = c >> 2, o8 = (c & 3) * 8;
            cp_async16((uint32_t)__cvta_generic_to_shared(&Bs[row * TSTRH + o8]),
                       &Bt[(size_t)(n0 + row) * Kd + k0 + o8]);
        }
    };

    issue_tile(0);
    asm volatile("cp.async.commit_group;");
    if (ntile > 1) issue_tile(1);
    asm volatile("cp.async.commit_group;");
    asm volatile("cp.async.wait_group 1;");
    __syncthreads();

    for (int t = 0; t < ntile; t++) {
        int s = t % STG;
        uint32_t sa = smb + (uint32_t)(s * STGH * 2);
        uint32_t aB = sa + (uint32_t)(((wm + arow_l) * TSTRH + acol_l) * 2);
        uint32_t bB = sa + (uint32_t)(AHALF * 2) +
                      (uint32_t)(((wn + brow_l) * TSTRH + bcol_l) * 2);

        if (t + 2 < ntile) issue_tile(t + 2);
        asm volatile("cp.async.commit_group;");

        #pragma unroll
        for (int kk = 0; kk < 2; kk++) {     // 2 x K=16 per 32-half tile
            uint32_t af[4][4], bf[4][2];
            #pragma unroll
            for (int mt = 0; mt < 4; mt++)
                ldsm_x4(af[mt][0], af[mt][1], af[mt][2], af[mt][3],
                        aB + mt * (16 * TSTRH * 2) + kk * 32);
            #pragma unroll
            for (int ntp = 0; ntp < 2; ntp++)
                ldsm_x4(bf[2 * ntp][0], bf[2 * ntp][1], bf[2 * ntp + 1][0], bf[2 * ntp + 1][1],
                        bB + ntp * (16 * TSTRH * 2) + kk * 32);
            #pragma unroll
            for (int mt = 0; mt < 4; mt++)
                #pragma unroll
                for (int nt = 0; nt < 4; nt++)
                    mma_f16(acc[mt][nt][0], acc[mt][nt][1], acc[mt][nt][2], acc[mt][nt][3],
                            af[mt][0], af[mt][1], af[mt][2], af[mt][3],
                            bf[nt][0], bf[nt][1]);
        }

        asm volatile("cp.async.wait_group 1;");
        __syncthreads();
    }

    // epilogue: c0,c1 at (m,n),(m,n+1); c2,c3 at (m+8,n),(m+8,n+1)
    #pragma unroll
    for (int mt = 0; mt < 4; mt++) {
        #pragma unroll
        for (int nt = 0; nt < 4; nt++) {
            int m = m0 + wm + mt * 16 + grp;
            int n = n0 + wn + nt * 8 + 2 * tig;
            float v00 = acc[mt][nt][0], v01 = acc[mt][nt][1];
            float v10 = acc[mt][nt][2], v11 = acc[mt][nt][3];
            if (FOUT) {
                float* C = (float*)Cv;
                if (resid) {
                    float2 r0 = *(const float2*)&resid[(size_t)m * ldc + n];
                    float2 r1 = *(const float2*)&resid[(size_t)(m + 8) * ldc + n];
                    v00 += r0.x; v01 += r0.y; v10 += r1.x; v11 += r1.y;
                }
                *(float2*)&C[(size_t)m * ldc + n]       = make_float2(v00, v01);
                *(float2*)&C[(size_t)(m + 8) * ldc + n] = make_float2(v10, v11);
            } else {
                __half* C = (__half*)Cv;
                if (gelu_src) {
                    __half2 h0 = *(const __half2*)&gelu_src[(size_t)m * ldc + n];
                    __half2 h1 = *(const __half2*)&gelu_src[(size_t)(m + 8) * ldc + n];
                    float g0 = __half2float(h0.x), g1 = __half2float(h0.y);
                    float g2 = __half2float(h1.x), g3 = __half2float(h1.y);
                    float t0 = tanhf(0.7978845608028654f * (g0 + 0.044715f * g0 * g0 * g0));
                    float t1 = tanhf(0.7978845608028654f * (g1 + 0.044715f * g1 * g1 * g1));
                    float t2 = tanhf(0.7978845608028654f * (g2 + 0.044715f * g2 * g2 * g2));
                    float t3 = tanhf(0.7978845608028654f * (g3 + 0.044715f * g3 * g3 * g3));
                    v00 *= 0.5f * g0 * (1.f + t0);
                    v01 *= 0.5f * g1 * (1.f + t1);
                    v10 *= 0.5f * g2 * (1.f + t2);
                    v11 *= 0.5f * g3 * (1.f + t3);
                }
                *(__half2*)&C[(size_t)m * ldc + n] =
                    __floats2half2_rn(v00, v01);
                *(__half2*)&C[(size_t)(m + 8) * ldc + n] =
                    __floats2half2_rn(v10, v11);
            }
        }
    }
}

// ---------------- RoPE (in place on half) ----------------
__global__ void rope_kernel(__half* __restrict__ x, const int* __restrict__ positions,
                            int heads, float outscale) {
    int row = blockIdx.x;
    int h   = blockIdx.y;
    int i   = threadIdx.x;  // 0..63
    float pos = (float)positions[row];
    float ts = powf(10000.f, (float)i / 64.f);
    float ang = pos / ts;
    float s, c;
    sincosf(ang, &s, &c);
    __half* p = x + ((size_t)row * heads + h) * HD;
    float x1 = __half2float(p[i]), x2 = __half2float(p[i + 64]);
    p[i]      = __float2half((x1 * c - x2 * s) * outscale);
    p[i + 64] = __float2half((x2 * c + x1 * s) * outscale);
}

// ---------------- Flash attention (fp16 mma + ldmatrix, causal) ----------
constexpr int FBQ = 64, FBS = 64;
constexpr int QKSTR = HD + 8;    // 136 halfs (272B rows: LDSM phases distinct)
constexpr int VTSTR = FBS + 8;   // 72 halfs (144B)
constexpr int PSTRH = FBS + 8;   // 72 halfs

__global__ __launch_bounds__(128, 2) void flash_f16_kernel(
    const __half* __restrict__ q, const __half* __restrict__ k,
    const __half* __restrict__ v) {

    int tq0 = blockIdx.x * FBQ;
    int n   = blockIdx.y;
    int b   = blockIdx.z;
    int kvh = n / GG;
    int tid  = threadIdx.x;
    int lane = tid & 31, warp = tid >> 5;
    int grp = lane >> 2, tig = lane & 3;
    int wq = warp * 16;

    __half* Qs = dynsmem_h;                 // [FBQ][QKSTR]
    __half* Ks = Qs + FBQ * QKSTR;          // [FBS][QKSTR]
    __half* Vt = Ks + FBS * QKSTR;          // [HD][VTSTR] (d-major)
    __half* Ps = Vt + HD * VTSTR;           // [4][16][PSTRH]
    __half* Pw = Ps + warp * 16 * PSTRH;

    int arow_l = (lane & 7) + ((lane >> 3) & 1) * 8;
    int acol_l = (lane >> 4) * 8;
    int brow_l = (lane & 7) + (lane >> 4) * 8;
    int bcol_l = ((lane >> 3) & 1) * 8;

    uint32_t qB = (uint32_t)__cvta_generic_to_shared(Qs) +
                  (uint32_t)(((wq + arow_l) * QKSTR + acol_l) * 2);
    uint32_t kB = (uint32_t)__cvta_generic_to_shared(Ks) +
                  (uint32_t)((brow_l * QKSTR + bcol_l) * 2);
    uint32_t vB = (uint32_t)__cvta_generic_to_shared(Vt) +
                  (uint32_t)((brow_l * VTSTR + bcol_l) * 2);
    uint32_t pB = (uint32_t)__cvta_generic_to_shared(Pw) +
                  (uint32_t)((arow_l * PSTRH + acol_l) * 2);

    // load Q tile: 64 rows x 256B = 1024 16B-chunks, 8/thread
    #pragma unroll
    for (int j = 0; j < 8; j++) {
        int c = tid + j * 128;
        int row = c >> 4, o8 = (c & 15) * 8;
        cp_async16((uint32_t)__cvta_generic_to_shared(&Qs[row * QKSTR + o8]),
                   &q[(((size_t)b * Tt + tq0 + row) * NH + n) * HD + o8]);
    }
    asm volatile("cp.async.commit_group;");

    float m0v = -1e30f, m1v = -1e30f, l0 = 0.f, l1 = 0.f;
    float O[16][4];
    #pragma unroll
    for (int nt = 0; nt < 16; nt++)
        #pragma unroll
        for (int r = 0; r < 4; r++) O[nt][r] = 0.f;

    int ntiles = blockIdx.x + 1;
    for (int kt = 0; kt < ntiles; kt++) {
        int s0 = kt * FBS;
        __syncthreads();
        // K: 64 rows x 128 halfs = 1024 16B-chunks, 8/thread
        #pragma unroll
        for (int j = 0; j < 8; j++) {
            int c = tid + j * 128;
            int row = c >> 4, o8 = (c & 15) * 8;
            cp_async16((uint32_t)__cvta_generic_to_shared(&Ks[row * QKSTR + o8]),
                       &k[(((size_t)b * Tt + s0 + row) * KHn + kvh) * HD + o8]);
        }
        asm volatile("cp.async.commit_group;");
        // V transposed into Vt[d][s]
        #pragma unroll
        for (int j = 0; j < 8; j++) {
            int c = tid + j * 128;
            int s = c >> 4, d0 = (c & 15) * 8;
            uint4 raw = *(const uint4*)&v[(((size_t)b * Tt + s0 + s) * KHn + kvh) * HD + d0];
            __half hv[8];
            *(uint4*)hv = raw;
            #pragma unroll
            for (int i = 0; i < 8; i++)
                Vt[(d0 + i) * VTSTR + s] = hv[i];
        }
        asm volatile("cp.async.wait_group 0;");
        __syncthreads();

        // ---- S = Q K^T
        float sc[8][4];
        #pragma unroll
        for (int nt = 0; nt < 8; nt++)
            #pragma unroll
            for (int r = 0; r < 4; r++) sc[nt][r] = 0.f;

        #pragma unroll
        for (int kk = 0; kk < 8; kk++) {     // HD/16
            uint32_t a0, a1, a2, a3;
            ldsm_x4(a0, a1, a2, a3, qB + kk * 32);
            uint32_t bf[8][2];
            #pragma unroll
            for (int ntp = 0; ntp < 4; ntp++)
                ldsm_x4(bf[2 * ntp][0], bf[2 * ntp][1], bf[2 * ntp + 1][0], bf[2 * ntp + 1][1],
                        kB + ntp * (16 * QKSTR * 2) + kk * 32);
            #pragma unroll
            for (int nt = 0; nt < 8; nt++)
                mma_f16(sc[nt][0], sc[nt][1], sc[nt][2], sc[nt][3],
                        a0, a1, a2, a3, bf[nt][0], bf[nt][1]);
        }

        int q0 = tq0 + wq + grp, q1 = q0 + 8;
        #pragma unroll
        for (int nt = 0; nt < 8; nt++) {
            int s = s0 + nt * 8 + 2 * tig;
            if (s     > q0) sc[nt][0] = -1e30f;
            if (s + 1 > q0) sc[nt][1] = -1e30f;
            if (s     > q1) sc[nt][2] = -1e30f;
            if (s + 1 > q1) sc[nt][3] = -1e30f;
        }

        float r0 = -1e30f, r1 = -1e30f;
        #pragma unroll
        for (int nt = 0; nt < 8; nt++) {
            r0 = fmaxf(r0, fmaxf(sc[nt][0], sc[nt][1]));
            r1 = fmaxf(r1, fmaxf(sc[nt][2], sc[nt][3]));
        }
        #pragma unroll
        for (int off = 1; off <= 2; off <<= 1) {
            r0 = fmaxf(r0, __shfl_xor_sync(0xffffffffu, r0, off));
            r1 = fmaxf(r1, __shfl_xor_sync(0xffffffffu, r1, off));
        }
        float mn0 = fmaxf(m0v, r0), mn1 = fmaxf(m1v, r1);
        float al0 = __expf(m0v - mn0), al1 = __expf(m1v - mn1);
        m0v = mn0; m1v = mn1;

        float rs0 = 0.f, rs1 = 0.f;
        uint32_t* PwU = (uint32_t*)Pw;
        #pragma unroll
        for (int nt = 0; nt < 8; nt++) {
            float p0 = __expf(sc[nt][0] - m0v);
            float p1 = __expf(sc[nt][1] - m0v);
            float p2 = __expf(sc[nt][2] - m1v);
            float p3 = __expf(sc[nt][3] - m1v);
            rs0 += p0 + p1; rs1 += p2 + p3;
            __half2 h0 = __floats2half2_rn(p0, p1);
            __half2 h1 = __floats2half2_rn(p2, p3);
            PwU[grp * 36 + nt * 4 + tig]       = *(uint32_t*)&h0;
            PwU[(grp + 8) * 36 + nt * 4 + tig] = *(uint32_t*)&h1;
        }
        #pragma unroll
        for (int off = 1; off <= 2; off <<= 1) {
            rs0 += __shfl_xor_sync(0xffffffffu, rs0, off);
            rs1 += __shfl_xor_sync(0xffffffffu, rs1, off);
        }
        l0 = l0 * al0 + rs0;
        l1 = l1 * al1 + rs1;

        #pragma unroll
        for (int nt = 0; nt < 16; nt++) {
            O[nt][0] *= al0; O[nt][1] *= al0;
            O[nt][2] *= al1; O[nt][3] *= al1;
        }

        __syncwarp();
        // ---- O += P V
        #pragma unroll
        for (int kk = 0; kk < 4; kk++) {     // FBS/16
            uint32_t a0, a1, a2, a3;
            ldsm_x4(a0, a1, a2, a3, pB + kk * 32);
            #pragma unroll
            for (int ntp = 0; ntp < 8; ntp++) {
                uint32_t b00, b01, b10, b11;
                ldsm_x4(b00, b01, b10, b11,
                        vB + ntp * (16 * VTSTR * 2) + kk * 32);
                mma_f16(O[2 * ntp][0], O[2 * ntp][1], O[2 * ntp][2], O[2 * ntp][3],
                        a0, a1, a2, a3, b00, b01);
                mma_f16(O[2 * ntp + 1][0], O[2 * ntp + 1][1], O[2 * ntp + 1][2], O[2 * ntp + 1][3],
                        a0, a1, a2, a3, b10, b11);
            }
        }
    }

    float il0 = 1.f / l0, il1 = 1.f / l1;
    int qr0 = tq0 + wq + grp, qr1 = qr0 + 8;
    #pragma unroll
    for (int nt = 0; nt < 16; nt++) {
        int c = nt * 8 + 2 * tig;
        *(__half2*)&g_enc[(((size_t)b * Tt + qr0) * NH + n) * HD + c] =
            __floats2half2_rn(O[nt][0] * il0, O[nt][1] * il0);
        *(__half2*)&g_enc[(((size_t)b * Tt + qr1) * NH + n) * HD + c] =
            __floats2half2_rn(O[nt][2] * il1, O[nt][3] * il1);
    }
}

// ---------------- launch ----------------
extern "C" void kernel_launch(void* const* d_in, const int* in_sizes, int n_in,
                              void* d_out, int out_size) {
    const float* x        = (const float*)d_in[0];
    const int*   pos      = (const int*)  d_in[1];
    // d_in[2] attn_mask: causal, recomputed in-kernel
    const float* w_q      = (const float*)d_in[3];
    const float* w_kv     = (const float*)d_in[4];
    const float* w_av     = (const float*)d_in[5];
    const float* s_attn   = (const float*)d_in[6];
    const float* s_ffw    = (const float*)d_in[7];
    const float* w_gating = (const float*)d_in[8];
    const float* w_linear = (const float*)d_in[9];
    float* out = (float*)d_out;

    __half *xn, *qp, *kp, *vp, *encp, *hp, *gatep, *wc;
    float *resp;
    cudaGetSymbolAddress((void**)&xn,    g_xn);
    cudaGetSymbolAddress((void**)&qp,    g_q);
    cudaGetSymbolAddress((void**)&kp,    g_k);
    cudaGetSymbolAddress((void**)&vp,    g_v);
    cudaGetSymbolAddress((void**)&encp,  g_enc);
    cudaGetSymbolAddress((void**)&resp,  g_res);
    cudaGetSymbolAddress((void**)&hp,    g_h);
    cudaGetSymbolAddress((void**)&gatep, g_gate);
    cudaGetSymbolAddress((void**)&wc,    g_w);

    cudaFuncSetAttribute(gemm_f16_kernel<0>, cudaFuncAttributeMaxDynamicSharedMemorySize, GEMM_SMEM);
    cudaFuncSetAttribute(gemm_f16_kernel<1>, cudaFuncAttributeMaxDynamicSharedMemorySize, GEMM_SMEM);

    // 0. transpose + fp16 weights to [N][K]
    dim3 tb(32, 8);
    transpose_cvt_kernel<<<dim3(HD / 32, Dd / 32, NH),      tb>>>(w_q,      wc + WQ_OFF,  Dd, HD);
    transpose_cvt_kernel<<<dim3(HD / 32, Dd / 32, 2 * KHn), tb>>>(w_kv,     wc + WKV_OFF, Dd, HD);
    transpose_cvt_kernel<<<dim3(Dd / 32, (NH * HD) / 32, 1),tb>>>(w_av,     wc + WAV_OFF, NH * HD, Dd);
    transpose_cvt_kernel<<<dim3(FF / 32, Dd / 32, 2),       tb>>>(w_gating, wc + WG_OFF,  Dd, FF);
    transpose_cvt_kernel<<<dim3(Dd / 32, FF / 32, 1),       tb>>>(w_linear, wc + WL_OFF,  FF, Dd);

    // 1. pre-attn rmsnorm -> half
    rmsnorm_kernel<<<Mtot, 256>>>(x, s_attn, xn);

    // 2. projections (half in/out)
    gemm_f16_kernel<0><<<dim3((NH * HD) / GN, Mtot / GM), 256, GEMM_SMEM>>>(
        xn, wc + WQ_OFF, nullptr, nullptr, qp, Dd, NH * HD);
    gemm_f16_kernel<0><<<dim3((KHn * HD) / GN, Mtot / GM), 256, GEMM_SMEM>>>(
        xn, wc + WKV_OFF, nullptr, nullptr, kp, Dd, KHn * HD);
    gemm_f16_kernel<0><<<dim3((KHn * HD) / GN, Mtot / GM), 256, GEMM_SMEM>>>(
        xn, wc + WKV_OFF + (size_t)KHn * Dd * HD, nullptr, nullptr, vp, Dd, KHn * HD);

    // 3. rope
    rope_kernel<<<dim3(Mtot, NH), 64>>>(qp, pos, NH, 0.08838834764831845f); // H^-0.5
    rope_kernel<<<dim3(Mtot, KHn), 64>>>(kp, pos, KHn, 1.f);

    // 4. flash attention
    int fa_smem = (FBQ * QKSTR + FBS * QKSTR + HD * VTSTR + 4 * 16 * PSTRH) * 2;
    cudaFuncSetAttribute(flash_f16_kernel, cudaFuncAttributeMaxDynamicSharedMemorySize, fa_smem);
    flash_f16_kernel<<<dim3(Tt / FBQ, NH, Bc), 128, fa_smem>>>(qp, kp, vp);

    // 5. attn output proj + residual (float out)
    gemm_f16_kernel<1><<<dim3(Dd / GN, Mtot / GM), 256, GEMM_SMEM>>>(
        encp, wc + WAV_OFF, x, nullptr, resp, NH * HD, Dd);

    // 6. pre-ffw rmsnorm -> half
    rmsnorm_kernel<<<Mtot, 256>>>(resp, s_ffw, hp);

    // 7. gate GEMM, then up GEMM with fused gelu(gate)*up -> gatep (in place)
    gemm_f16_kernel<0><<<dim3(FF / GN, Mtot / GM), 256, GEMM_SMEM>>>(
        hp, wc + WG_OFF, nullptr, nullptr, gatep, Dd, FF);
    gemm_f16_kernel<0><<<dim3(FF / GN, Mtot / GM), 256, GEMM_SMEM>>>(
        hp, wc + WG_OFF + (size_t)Dd * FF, nullptr, gatep, gatep, Dd, FF);

    // 8. down proj + residual -> out (float)
    gemm_f16_kernel<1><<<dim3(Dd / GN, Mtot / GM), 256, GEMM_SMEM>>>(
        gatep, wc + WL_OFF, resp, nullptr, out, FF, Dd);
}

// round 14
// speedup vs baseline: 2.1005x; 1.0285x over previous
#include <cuda_runtime.h>
#include <cuda_fp16.h>
#include <math.h>
#include <stdint.h>

// Problem constants
constexpr int Bc  = 2;
constexpr int Tt  = 2048;
constexpr int Dd  = 2048;
constexpr int NH  = 16;   // query heads
constexpr int KHn = 8;    // kv heads
constexpr int HD  = 128;  // head dim
constexpr int FF  = 8192; // ffw dim
constexpr int Mtot = Bc * Tt;      // 4096
constexpr int GG  = NH / KHn;      // 2

// -------- scratch (static device globals; no allocations) --------
__device__ __half g_xn  [(size_t)Mtot * Dd];
__device__ __half g_q   [(size_t)Mtot * NH * HD];
__device__ __half g_k   [(size_t)Mtot * KHn * HD];
__device__ __half g_v   [(size_t)Mtot * KHn * HD];
__device__ __half g_enc [(size_t)Mtot * NH * HD];
__device__ float  g_res [(size_t)Mtot * Dd];
__device__ __half g_h   [(size_t)Mtot * Dd];
__device__ __half g_gate[(size_t)Mtot * FF];
// transposed fp16 weights, layout [N][K] K-major
constexpr size_t WQ_OFF  = 0;
constexpr size_t WKV_OFF = WQ_OFF  + (size_t)NH * Dd * HD;
constexpr size_t WAV_OFF = WKV_OFF + (size_t)2 * KHn * Dd * HD;
constexpr size_t WG_OFF  = WAV_OFF + (size_t)NH * HD * Dd;
constexpr size_t WL_OFF  = WG_OFF  + (size_t)2 * Dd * FF;
constexpr size_t WTOT    = WL_OFF  + (size_t)FF * Dd;
__device__ __half g_w[WTOT];

__device__ __forceinline__ void cp_async16(uint32_t smem_addr, const void* gptr) {
    asm volatile("cp.async.cg.shared.global [%0], [%1], 16;" :: "r"(smem_addr), "l"(gptr));
}
__device__ __forceinline__ void mma_f16(float& c0, float& c1, float& c2, float& c3,
                                        uint32_t a0, uint32_t a1, uint32_t a2, uint32_t a3,
                                        uint32_t b0, uint32_t b1) {
    asm volatile(
        "mma.sync.aligned.m16n8k16.row.col.f32.f16.f16.f32 "
        "{%0,%1,%2,%3}, {%4,%5,%6,%7}, {%8,%9}, {%0,%1,%2,%3};"
        : "+f"(c0), "+f"(c1), "+f"(c2), "+f"(c3)
        : "r"(a0), "r"(a1), "r"(a2), "r"(a3), "r"(b0), "r"(b1));
}
__device__ __forceinline__ void ldsm_x4(uint32_t& r0, uint32_t& r1, uint32_t& r2, uint32_t& r3,
                                        uint32_t addr) {
    asm volatile("ldmatrix.sync.aligned.m8n8.x4.shared.b16 {%0,%1,%2,%3}, [%4];"
                 : "=r"(r0), "=r"(r1), "=r"(r2), "=r"(r3) : "r"(addr));
}

// ---------------- batched transpose + fp16: in[b][K][N] f32 -> out[b][N][K] f16
// half-typed smem transpose with half2-vectorized global writes.
__global__ void transpose_cvt_kernel(const float* __restrict__ src,
                                     __half* __restrict__ dst, int K, int N) {
    __shared__ __half tile[32][34];   // tile[n][k]; stride 34 halfs (17 words, 17⊥32)
    src += (size_t)blockIdx.z * K * N;
    dst += (size_t)blockIdx.z * K * N;
    int n0 = blockIdx.x * 32, k0 = blockIdx.y * 32;
    int tx = threadIdx.x, ty = threadIdx.y;  // 32 x 8
    int tid = ty * 32 + tx;
    #pragma unroll
    for (int i = 0; i < 32; i += 8)
        tile[tx][ty + i] = __float2half(src[(size_t)(k0 + ty + i) * N + n0 + tx]);
    __syncthreads();
    #pragma unroll
    for (int j = 0; j < 2; j++) {
        int idx = tid + j * 256;
        int nl = idx >> 4, kp = (idx & 15) * 2;
        *(__half2*)&dst[(size_t)(n0 + nl) * K + k0 + kp] = *(__half2*)&tile[nl][kp];
    }
}

// ---------------- RMSNorm: float in -> half out ----------------
__global__ void rmsnorm_kernel(const float* __restrict__ x,
                               const float* __restrict__ scale,
                               __half* __restrict__ out) {
    int row = blockIdx.x;
    const float* xr = x + (size_t)row * Dd;
    float ss = 0.f;
    for (int i = threadIdx.x; i < Dd; i += blockDim.x) {
        float v = xr[i];
        ss += v * v;
    }
    __shared__ float red[32];
    #pragma unroll
    for (int o = 16; o; o >>= 1) ss += __shfl_xor_sync(0xffffffffu, ss, o);
    if ((threadIdx.x & 31) == 0) red[threadIdx.x >> 5] = ss;
    __syncthreads();
    if (threadIdx.x < 32) {
        float v = (threadIdx.x < (blockDim.x >> 5)) ? red[threadIdx.x] : 0.f;
        #pragma unroll
        for (int o = 16; o; o >>= 1) v += __shfl_xor_sync(0xffffffffu, v, o);
        if (threadIdx.x == 0) red[0] = v;
    }
    __syncthreads();
    float inv = rsqrtf(red[0] / (float)Dd + 1e-6f);
    __half* outr = out + (size_t)row * Dd;
    for (int i = threadIdx.x; i < Dd; i += blockDim.x)
        outr[i] = __float2half(xr[i] * inv * (1.f + scale[i]));
}

// ======= FP16 mma GEMM: C = A[M,Kd] @ Bt[N,Kd]^T (ldmatrix, K-tile 64) =======
constexpr int GM = 128, GN = 128, GK = 64;
constexpr int TSTRH = 72;              // halfs/row (144B: LDSM phases 16r mod 128 distinct)
constexpr int STG  = 3;
constexpr int AHALF = GM * TSTRH;
constexpr int BHALF = GN * TSTRH;
constexpr int STGH  = AHALF + BHALF;
constexpr int GEMM_SMEM = STG * STGH * 2;   // 110592 B -> still 2 CTAs/SM

extern __shared__ __half dynsmem_h[];

// FOUT=1: float C (+resid). FOUT=0: half C (+optional gelu-gate multiply).
template <int FOUT>
__global__ __launch_bounds__(256, 2) void gemm_f16_kernel(
    const __half* __restrict__ A, const __half* __restrict__ Bt,
    const float* __restrict__ resid, const __half* __restrict__ gelu_src,
    void* __restrict__ Cv, int Kd, int ldc) {

    __half* smem = dynsmem_h;
    uint32_t smb = (uint32_t)__cvta_generic_to_shared(dynsmem_h);
    int m0 = blockIdx.y * GM, n0 = blockIdx.x * GN;
    int tid  = threadIdx.x;
    int lane = tid & 31, warp = tid >> 5;
    int grp = lane >> 2, tig = lane & 3;
    int wm = (warp >> 2) * 64;
    int wn = (warp & 3) * 32;

    int arow_l = (lane & 7) + ((lane >> 3) & 1) * 8;
    int acol_l = (lane >> 4) * 8;
    int brow_l = (lane & 7) + (lane >> 4) * 8;
    int bcol_l = ((lane >> 3) & 1) * 8;

    float acc[4][4][4];
    #pragma unroll
    for (int mt = 0; mt < 4; mt++)
        #pragma unroll
        for (int nt = 0; nt < 4; nt++)
            #pragma unroll
            for (int r = 0; r < 4; r++) acc[mt][nt][r] = 0.f;

    int ntile = Kd / GK;

    // per tile: A 128 rows x 128B = 1024 chunks (4/thread), B same
    auto issue_tile = [&](int t) {
        int s = t % STG;
        int k0 = t * GK;
        __half* As = smem + (size_t)s * STGH;
        __half* Bs = As + AHALF;
        #pragma unroll
        for (int j = 0; j < 4; j++) {
            int c = tid + j * 256;
            int row = c >> 3, o8 = (c & 7) * 8;
            cp_async16((uint32_t)__cvta_generic_to_shared(&As[row * TSTRH + o8]),
                       &A[(size_t)(m0 + row) * Kd + k0 + o8]);
        }
        #pragma unroll
        for (int j = 0; j < 4; j++) {
            int c = tid + j * 256;
            int row = c >> 3, o8 = (c & 7) * 8;
            cp_async16((uint32_t)__cvta_generic_to_shared(&Bs[row * TSTRH + o8]),
                       &Bt[(size_t)(n0 + row) * Kd + k0 + o8]);
        }
    };

    issue_tile(0);
    asm volatile("cp.async.commit_group;");
    if (ntile > 1) issue_tile(1);
    asm volatile("cp.async.commit_group;");
    asm volatile("cp.async.wait_group 1;");
    __syncthreads();

    for (int t = 0; t < ntile; t++) {
        int s = t % STG;
        uint32_t sa = smb + (uint32_t)(s * STGH * 2);
        uint32_t aB = sa + (uint32_t)(((wm + arow_l) * TSTRH + acol_l) * 2);
        uint32_t bB = sa + (uint32_t)(AHALF * 2) +
                      (uint32_t)(((wn + brow_l) * TSTRH + bcol_l) * 2);

        if (t + 2 < ntile) issue_tile(t + 2);
        asm volatile("cp.async.commit_group;");

        #pragma unroll
        for (int kk = 0; kk < 4; kk++) {     // 4 x K=16 per 64-half tile
            uint32_t af[4][4], bf[4][2];
            #pragma unroll
            for (int mt = 0; mt < 4; mt++)
                ldsm_x4(af[mt][0], af[mt][1], af[mt][2], af[mt][3],
                        aB + mt * (16 * TSTRH * 2) + kk * 32);
            #pragma unroll
            for (int ntp = 0; ntp < 2; ntp++)
                ldsm_x4(bf[2 * ntp][0], bf[2 * ntp][1], bf[2 * ntp + 1][0], bf[2 * ntp + 1][1],
                        bB + ntp * (16 * TSTRH * 2) + kk * 32);
            #pragma unroll
            for (int mt = 0; mt < 4; mt++)
                #pragma unroll
                for (int nt = 0; nt < 4; nt++)
                    mma_f16(acc[mt][nt][0], acc[mt][nt][1], acc[mt][nt][2], acc[mt][nt][3],
                            af[mt][0], af[mt][1], af[mt][2], af[mt][3],
                            bf[nt][0], bf[nt][1]);
        }

        asm volatile("cp.async.wait_group 1;");
        __syncthreads();
    }

    // epilogue
    #pragma unroll
    for (int mt = 0; mt < 4; mt++) {
        #pragma unroll
        for (int nt = 0; nt < 4; nt++) {
            int m = m0 + wm + mt * 16 + grp;
            int n = n0 + wn + nt * 8 + 2 * tig;
            float v00 = acc[mt][nt][0], v01 = acc[mt][nt][1];
            float v10 = acc[mt][nt][2], v11 = acc[mt][nt][3];
            if (FOUT) {
                float* C = (float*)Cv;
                if (resid) {
                    float2 r0 = *(const float2*)&resid[(size_t)m * ldc + n];
                    float2 r1 = *(const float2*)&resid[(size_t)(m + 8) * ldc + n];
                    v00 += r0.x; v01 += r0.y; v10 += r1.x; v11 += r1.y;
                }
                *(float2*)&C[(size_t)m * ldc + n]       = make_float2(v00, v01);
                *(float2*)&C[(size_t)(m + 8) * ldc + n] = make_float2(v10, v11);
            } else {
                __half* C = (__half*)Cv;
                if (gelu_src) {
                    __half2 h0 = *(const __half2*)&gelu_src[(size_t)m * ldc + n];
                    __half2 h1 = *(const __half2*)&gelu_src[(size_t)(m + 8) * ldc + n];
                    float g0 = __half2float(h0.x), g1 = __half2float(h0.y);
                    float g2 = __half2float(h1.x), g3 = __half2float(h1.y);
                    float t0 = tanhf(0.7978845608028654f * (g0 + 0.044715f * g0 * g0 * g0));
                    float t1 = tanhf(0.7978845608028654f * (g1 + 0.044715f * g1 * g1 * g1));
                    float t2 = tanhf(0.7978845608028654f * (g2 + 0.044715f * g2 * g2 * g2));
                    float t3 = tanhf(0.7978845608028654f * (g3 + 0.044715f * g3 * g3 * g3));
                    v00 *= 0.5f * g0 * (1.f + t0);
                    v01 *= 0.5f * g1 * (1.f + t1);
                    v10 *= 0.5f * g2 * (1.f + t2);
                    v11 *= 0.5f * g3 * (1.f + t3);
                }
                *(__half2*)&C[(size_t)m * ldc + n] =
                    __floats2half2_rn(v00, v01);
                *(__half2*)&C[(size_t)(m + 8) * ldc + n] =
                    __floats2half2_rn(v10, v11);
            }
        }
    }
}

// ---------------- RoPE (in place on half) ----------------
__global__ void rope_kernel(__half* __restrict__ x, const int* __restrict__ positions,
                            int heads, float outscale) {
    int row = blockIdx.x;
    int h   = blockIdx.y;
    int i   = threadIdx.x;  // 0..63
    float pos = (float)positions[row];
    float ts = powf(10000.f, (float)i / 64.f);
    float ang = pos / ts;
    float s, c;
    sincosf(ang, &s, &c);
    __half* p = x + ((size_t)row * heads + h) * HD;
    float x1 = __half2float(p[i]), x2 = __half2float(p[i + 64]);
    p[i]      = __float2half((x1 * c - x2 * s) * outscale);
    p[i + 64] = __float2half((x2 * c + x1 * s) * outscale);
}

// ---------------- Flash attention (fp16 mma + ldmatrix, causal) ----------
constexpr int FBQ = 64, FBS = 64;
constexpr int QKSTR = HD + 8;    // 136 halfs
constexpr int VTSTR = FBS + 8;   // 72 halfs
constexpr int PSTRH = FBS + 8;   // 72 halfs

__global__ __launch_bounds__(128, 2) void flash_f16_kernel(
    const __half* __restrict__ q, const __half* __restrict__ k,
    const __half* __restrict__ v) {

    int tq0 = blockIdx.x * FBQ;
    int n   = blockIdx.y;
    int b   = blockIdx.z;
    int kvh = n / GG;
    int tid  = threadIdx.x;
    int lane = tid & 31, warp = tid >> 5;
    int grp = lane >> 2, tig = lane & 3;
    int wq = warp * 16;

    __half* Qs = dynsmem_h;                 // [FBQ][QKSTR]
    __half* Ks = Qs + FBQ * QKSTR;          // [FBS][QKSTR]
    __half* Vt = Ks + FBS * QKSTR;          // [HD][VTSTR] (d-major)
    __half* Ps = Vt + HD * VTSTR;           // [4][16][PSTRH]
    __half* Pw = Ps + warp * 16 * PSTRH;

    int arow_l = (lane & 7) + ((lane >> 3) & 1) * 8;
    int acol_l = (lane >> 4) * 8;
    int brow_l = (lane & 7) + (lane >> 4) * 8;
    int bcol_l = ((lane >> 3) & 1) * 8;

    uint32_t qB = (uint32_t)__cvta_generic_to_shared(Qs) +
                  (uint32_t)(((wq + arow_l) * QKSTR + acol_l) * 2);
    uint32_t kB = (uint32_t)__cvta_generic_to_shared(Ks) +
                  (uint32_t)((brow_l * QKSTR + bcol_l) * 2);
    uint32_t vB = (uint32_t)__cvta_generic_to_shared(Vt) +
                  (uint32_t)((brow_l * VTSTR + bcol_l) * 2);
    uint32_t pB = (uint32_t)__cvta_generic_to_shared(Pw) +
                  (uint32_t)((arow_l * PSTRH + acol_l) * 2);

    #pragma unroll
    for (int j = 0; j < 8; j++) {
        int c = tid + j * 128;
        int row = c >> 4, o8 = (c & 15) * 8;
        cp_async16((uint32_t)__cvta_generic_to_shared(&Qs[row * QKSTR + o8]),
                   &q[(((size_t)b * Tt + tq0 + row) * NH + n) * HD + o8]);
    }
    asm volatile("cp.async.commit_group;");

    float m0v = -1e30f, m1v = -1e30f, l0 = 0.f, l1 = 0.f;
    float O[16][4];
    #pragma unroll
    for (int nt = 0; nt < 16; nt++)
        #pragma unroll
        for (int r = 0; r < 4; r++) O[nt][r] = 0.f;

    int ntiles = blockIdx.x + 1;
    for (int kt = 0; kt < ntiles; kt++) {
        int s0 = kt * FBS;
        __syncthreads();
        #pragma unroll
        for (int j = 0; j < 8; j++) {
            int c = tid + j * 128;
            int row = c >> 4, o8 = (c & 15) * 8;
            cp_async16((uint32_t)__cvta_generic_to_shared(&Ks[row * QKSTR + o8]),
                       &k[(((size_t)b * Tt + s0 + row) * KHn + kvh) * HD + o8]);
        }
        asm volatile("cp.async.commit_group;");
        #pragma unroll
        for (int j = 0; j < 8; j++) {
            int c = tid + j * 128;
            int s = c >> 4, d0 = (c & 15) * 8;
            uint4 raw = *(const uint4*)&v[(((size_t)b * Tt + s0 + s) * KHn + kvh) * HD + d0];
            __half hv[8];
            *(uint4*)hv = raw;
            #pragma unroll
            for (int i = 0; i < 8; i++)
                Vt[(d0 + i) * VTSTR + s] = hv[i];
        }
        asm volatile("cp.async.wait_group 0;");
        __syncthreads();

        float sc[8][4];
        #pragma unroll
        for (int nt = 0; nt < 8; nt++)
            #pragma unroll
            for (int r = 0; r < 4; r++) sc[nt][r] = 0.f;

        #pragma unroll
        for (int kk = 0; kk < 8; kk++) {
            uint32_t a0, a1, a2, a3;
            ldsm_x4(a0, a1, a2, a3, qB + kk * 32);
            uint32_t bf[8][2];
            #pragma unroll
            for (int ntp = 0; ntp < 4; ntp++)
                ldsm_x4(bf[2 * ntp][0], bf[2 * ntp][1], bf[2 * ntp + 1][0], bf[2 * ntp + 1][1],
                        kB + ntp * (16 * QKSTR * 2) + kk * 32);
            #pragma unroll
            for (int nt = 0; nt < 8; nt++)
                mma_f16(sc[nt][0], sc[nt][1], sc[nt][2], sc[nt][3],
                        a0, a1, a2, a3, bf[nt][0], bf[nt][1]);
        }

        int q0 = tq0 + wq + grp, q1 = q0 + 8;
        #pragma unroll
        for (int nt = 0; nt < 8; nt++) {
            int s = s0 + nt * 8 + 2 * tig;
            if (s     > q0) sc[nt][0] = -1e30f;
            if (s + 1 > q0) sc[nt][1] = -1e30f;
            if (s     > q1) sc[nt][2] = -1e30f;
            if (s + 1 > q1) sc[nt][3] = -1e30f;
        }

        float r0 = -1e30f, r1 = -1e30f;
        #pragma unroll
        for (int nt = 0; nt < 8; nt++) {
            r0 = fmaxf(r0, fmaxf(sc[nt][0], sc[nt][1]));
            r1 = fmaxf(r1, fmaxf(sc[nt][2], sc[nt][3]));
        }
        #pragma unroll
        for (int off = 1; off <= 2; off <<= 1) {
            r0 = fmaxf(r0, __shfl_xor_sync(0xffffffffu, r0, off));
            r1 = fmaxf(r1, __shfl_xor_sync(0xffffffffu, r1, off));
        }
        float mn0 = fmaxf(m0v, r0), mn1 = fmaxf(m1v, r1);
        float al0 = __expf(m0v - mn0), al1 = __expf(m1v - mn1);
        m0v = mn0; m1v = mn1;

        float rs0 = 0.f, rs1 = 0.f;
        uint32_t* PwU = (uint32_t*)Pw;
        #pragma unroll
        for (int nt = 0; nt < 8; nt++) {
            float p0 = __expf(sc[nt][0] - m0v);
            float p1 = __expf(sc[nt][1] - m0v);
            float p2 = __expf(sc[nt][2] - m1v);
            float p3 = __expf(sc[nt][3] - m1v);
            rs0 += p0 + p1; rs1 += p2 + p3;
            __half2 h0 = __floats2half2_rn(p0, p1);
            __half2 h1 = __floats2half2_rn(p2, p3);
            PwU[grp * 36 + nt * 4 + tig]       = *(uint32_t*)&h0;
            PwU[(grp + 8) * 36 + nt * 4 + tig] = *(uint32_t*)&h1;
        }
        #pragma unroll
        for (int off = 1; off <= 2; off <<= 1) {
            rs0 += __shfl_xor_sync(0xffffffffu, rs0, off);
            rs1 += __shfl_xor_sync(0xffffffffu, rs1, off);
        }
        l0 = l0 * al0 + rs0;
        l1 = l1 * al1 + rs1;

        #pragma unroll
        for (int nt = 0; nt < 16; nt++) {
            O[nt][0] *= al0; O[nt][1] *= al0;
            O[nt][2] *= al1; O[nt][3] *= al1;
        }

        __syncwarp();
        #pragma unroll
        for (int kk = 0; kk < 4; kk++) {
            uint32_t a0, a1, a2, a3;
            ldsm_x4(a0, a1, a2, a3, pB + kk * 32);
            #pragma unroll
            for (int ntp = 0; ntp < 8; ntp++) {
                uint32_t b00, b01, b10, b11;
                ldsm_x4(b00, b01, b10, b11,
                        vB + ntp * (16 * VTSTR * 2) + kk * 32);
                mma_f16(O[2 * ntp][0], O[2 * ntp][1], O[2 * ntp][2], O[2 * ntp][3],
                        a0, a1, a2, a3, b00, b01);
                mma_f16(O[2 * ntp + 1][0], O[2 * ntp + 1][1], O[2 * ntp + 1][2], O[2 * ntp + 1][3],
                        a0, a1, a2, a3, b10, b11);
            }
        }
    }

    float il0 = 1.f / l0, il1 = 1.f / l1;
    int qr0 = tq0 + wq + grp, qr1 = qr0 + 8;
    #pragma unroll
    for (int nt = 0; nt < 16; nt++) {
        int c = nt * 8 + 2 * tig;
        *(__half2*)&g_enc[(((size_t)b * Tt + qr0) * NH + n) * HD + c] =
            __floats2half2_rn(O[nt][0] * il0, O[nt][1] * il0);
        *(__half2*)&g_enc[(((size_t)b * Tt + qr1) * NH + n) * HD + c] =
            __floats2half2_rn(O[nt][2] * il1, O[nt][3] * il1);
    }
}

// ---------------- launch ----------------
extern "C" void kernel_launch(void* const* d_in, const int* in_sizes, int n_in,
                              void* d_out, int out_size) {
    const float* x        = (const float*)d_in[0];
    const int*   pos      = (const int*)  d_in[1];
    // d_in[2] attn_mask: causal, recomputed in-kernel
    const float* w_q      = (const float*)d_in[3];
    const float* w_kv     = (const float*)d_in[4];
    const float* w_av     = (const float*)d_in[5];
    const float* s_attn   = (const float*)d_in[6];
    const float* s_ffw    = (const float*)d_in[7];
    const float* w_gating = (const float*)d_in[8];
    const float* w_linear = (const float*)d_in[9];
    float* out = (float*)d_out;

    __half *xn, *qp, *kp, *vp, *encp, *hp, *gatep, *wc;
    float *resp;
    cudaGetSymbolAddress((void**)&xn,    g_xn);
    cudaGetSymbolAddress((void**)&qp,    g_q);
    cudaGetSymbolAddress((void**)&kp,    g_k);
    cudaGetSymbolAddress((void**)&vp,    g_v);
    cudaGetSymbolAddress((void**)&encp,  g_enc);
    cudaGetSymbolAddress((void**)&resp,  g_res);
    cudaGetSymbolAddress((void**)&hp,    g_h);
    cudaGetSymbolAddress((void**)&gatep, g_gate);
    cudaGetSymbolAddress((void**)&wc,    g_w);

    cudaFuncSetAttribute(gemm_f16_kernel<0>, cudaFuncAttributeMaxDynamicSharedMemorySize, GEMM_SMEM);
    cudaFuncSetAttribute(gemm_f16_kernel<1>, cudaFuncAttributeMaxDynamicSharedMemorySize, GEMM_SMEM);

    // 0. transpose + fp16 weights to [N][K]
    dim3 tb(32, 8);
    transpose_cvt_kernel<<<dim3(HD / 32, Dd / 32, NH),      tb>>>(w_q,      wc + WQ_OFF,  Dd, HD);
    transpose_cvt_kernel<<<dim3(HD / 32, Dd / 32, 2 * KHn), tb>>>(w_kv,     wc + WKV_OFF, Dd, HD);
    transpose_cvt_kernel<<<dim3(Dd / 32, (NH * HD) / 32, 1),tb>>>(w_av,     wc + WAV_OFF, NH * HD, Dd);
    transpose_cvt_kernel<<<dim3(FF / 32, Dd / 32, 2),       tb>>>(w_gating, wc + WG_OFF,  Dd, FF);
    transpose_cvt_kernel<<<dim3(Dd / 32, FF / 32, 1),       tb>>>(w_linear, wc + WL_OFF,  FF, Dd);

    // 1. pre-attn rmsnorm -> half
    rmsnorm_kernel<<<Mtot, 256>>>(x, s_attn, xn);

    // 2. projections (half in/out)
    gemm_f16_kernel<0><<<dim3((NH * HD) / GN, Mtot / GM), 256, GEMM_SMEM>>>(
        xn, wc + WQ_OFF, nullptr, nullptr, qp, Dd, NH * HD);
    gemm_f16_kernel<0><<<dim3((KHn * HD) / GN, Mtot / GM), 256, GEMM_SMEM>>>(
        xn, wc + WKV_OFF, nullptr, nullptr, kp, Dd, KHn * HD);
    gemm_f16_kernel<0><<<dim3((KHn * HD) / GN, Mtot / GM), 256, GEMM_SMEM>>>(
        xn, wc + WKV_OFF + (size_t)KHn * Dd * HD, nullptr, nullptr, vp, Dd, KHn * HD);

    // 3. rope
    rope_kernel<<<dim3(Mtot, NH), 64>>>(qp, pos, NH, 0.08838834764831845f); // H^-0.5
    rope_kernel<<<dim3(Mtot, KHn), 64>>>(kp, pos, KHn, 1.f);

    // 4. flash attention
    int fa_smem = (FBQ * QKSTR + FBS * QKSTR + HD * VTSTR + 4 * 16 * PSTRH) * 2;
    cudaFuncSetAttribute(flash_f16_kernel, cudaFuncAttributeMaxDynamicSharedMemorySize, fa_smem);
    flash_f16_kernel<<<dim3(Tt / FBQ, NH, Bc), 128, fa_smem>>>(qp, kp, vp);

    // 5. attn output proj + residual (float out)
    gemm_f16_kernel<1><<<dim3(Dd / GN, Mtot / GM), 256, GEMM_SMEM>>>(
        encp, wc + WAV_OFF, x, nullptr, resp, NH * HD, Dd);

    // 6. pre-ffw rmsnorm -> half
    rmsnorm_kernel<<<Mtot, 256>>>(resp, s_ffw, hp);

    // 7. gate GEMM, then up GEMM with fused gelu(gate)*up -> gatep (in place)
    gemm_f16_kernel<0><<<dim3(FF / GN, Mtot / GM), 256, GEMM_SMEM>>>(
        hp, wc + WG_OFF, nullptr, nullptr, gatep, Dd, FF);
    gemm_f16_kernel<0><<<dim3(FF / GN, Mtot / GM), 256, GEMM_SMEM>>>(
        hp, wc + WG_OFF + (size_t)Dd * FF, nullptr, gatep, gatep, Dd, FF);

    // 8. down proj + residual -> out (float)
    gemm_f16_kernel<1><<<dim3(Dd / GN, Mtot / GM), 256, GEMM_SMEM>>>(
        gatep, wc + WL_OFF, resp, nullptr, out, FF, Dd);
}

// round 16
// speedup vs baseline: 2.1367x; 1.0173x over previous
#include <cuda_runtime.h>
#include <cuda_fp16.h>
#include <math.h>
#include <stdint.h>

// Problem constants
constexpr int Bc  = 2;
constexpr int Tt  = 2048;
constexpr int Dd  = 2048;
constexpr int NH  = 16;   // query heads
constexpr int KHn = 8;    // kv heads
constexpr int HD  = 128;  // head dim
constexpr int FF  = 8192; // ffw dim
constexpr int Mtot = Bc * Tt;      // 4096
constexpr int GG  = NH / KHn;      // 2
constexpr int QKV = (NH + 2 * KHn) * HD;   // 4096 (q | k | v columns)

// -------- scratch (static device globals; no allocations) --------
__device__ __half g_xn  [(size_t)Mtot * Dd];
__device__ __half g_qkv [(size_t)Mtot * QKV];
__device__ __half g_enc [(size_t)Mtot * NH * HD];
__device__ float  g_res [(size_t)Mtot * Dd];
__device__ __half g_h   [(size_t)Mtot * Dd];
__device__ __half g_gate[(size_t)Mtot * FF];
// transposed fp16 weights, layout [N][K] K-major. wq|wk|wv rows are contiguous.
constexpr size_t WQ_OFF  = 0;
constexpr size_t WKV_OFF = WQ_OFF  + (size_t)NH * Dd * HD;
constexpr size_t WAV_OFF = WKV_OFF + (size_t)2 * KHn * Dd * HD;
constexpr size_t WG_OFF  = WAV_OFF + (size_t)NH * HD * Dd;
constexpr size_t WL_OFF  = WG_OFF  + (size_t)2 * Dd * FF;
constexpr size_t WTOT    = WL_OFF  + (size_t)FF * Dd;
__device__ __half g_w[WTOT];

__device__ __forceinline__ void cp_async16(uint32_t smem_addr, const void* gptr) {
    asm volatile("cp.async.cg.shared.global [%0], [%1], 16;" :: "r"(smem_addr), "l"(gptr));
}
__device__ __forceinline__ void mma_f16(float& c0, float& c1, float& c2, float& c3,
                                        uint32_t a0, uint32_t a1, uint32_t a2, uint32_t a3,
                                        uint32_t b0, uint32_t b1) {
    asm volatile(
        "mma.sync.aligned.m16n8k16.row.col.f32.f16.f16.f32 "
        "{%0,%1,%2,%3}, {%4,%5,%6,%7}, {%8,%9}, {%0,%1,%2,%3};"
        : "+f"(c0), "+f"(c1), "+f"(c2), "+f"(c3)
        : "r"(a0), "r"(a1), "r"(a2), "r"(a3), "r"(b0), "r"(b1));
}
__device__ __forceinline__ void ldsm_x4(uint32_t& r0, uint32_t& r1, uint32_t& r2, uint32_t& r3,
                                        uint32_t addr) {
    asm volatile("ldmatrix.sync.aligned.m8n8.x4.shared.b16 {%0,%1,%2,%3}, [%4];"
                 : "=r"(r0), "=r"(r1), "=r"(r2), "=r"(r3) : "r"(addr));
}
__device__ __forceinline__ float tanh_fast(float x) {
    float y;
    asm("tanh.approx.f32 %0, %1;" : "=f"(y) : "f"(x));
    return y;
}
__device__ __forceinline__ float gelu_f(float g) {
    return 0.5f * g * (1.f + tanh_fast(0.7978845608028654f * (g + 0.044715f * g * g * g)));
}

// ---------------- batched transpose + fp16: in[b][K][N] f32 -> out[b][N][K] f16
__global__ void transpose_cvt_kernel(const float* __restrict__ src,
                                     __half* __restrict__ dst, int K, int N) {
    __shared__ __half tile[32][34];
    src += (size_t)blockIdx.z * K * N;
    dst += (size_t)blockIdx.z * K * N;
    int n0 = blockIdx.x * 32, k0 = blockIdx.y * 32;
    int tx = threadIdx.x, ty = threadIdx.y;  // 32 x 8
    int tid = ty * 32 + tx;
    #pragma unroll
    for (int i = 0; i < 32; i += 8)
        tile[tx][ty + i] = __float2half(src[(size_t)(k0 + ty + i) * N + n0 + tx]);
    __syncthreads();
    #pragma unroll
    for (int j = 0; j < 2; j++) {
        int idx = tid + j * 256;
        int nl = idx >> 4, kp = (idx & 15) * 2;
        *(__half2*)&dst[(size_t)(n0 + nl) * K + k0 + kp] = *(__half2*)&tile[nl][kp];
    }
}

// ---------------- RMSNorm: float in -> half out ----------------
__global__ void rmsnorm_kernel(const float* __restrict__ x,
                               const float* __restrict__ scale,
                               __half* __restrict__ out) {
    int row = blockIdx.x;
    const float* xr = x + (size_t)row * Dd;
    float ss = 0.f;
    for (int i = threadIdx.x; i < Dd; i += blockDim.x) {
        float v = xr[i];
        ss += v * v;
    }
    __shared__ float red[32];
    #pragma unroll
    for (int o = 16; o; o >>= 1) ss += __shfl_xor_sync(0xffffffffu, ss, o);
    if ((threadIdx.x & 31) == 0) red[threadIdx.x >> 5] = ss;
    __syncthreads();
    if (threadIdx.x < 32) {
        float v = (threadIdx.x < (blockDim.x >> 5)) ? red[threadIdx.x] : 0.f;
        #pragma unroll
        for (int o = 16; o; o >>= 1) v += __shfl_xor_sync(0xffffffffu, v, o);
        if (threadIdx.x == 0) red[0] = v;
    }
    __syncthreads();
    float inv = rsqrtf(red[0] / (float)Dd + 1e-6f);
    __half* outr = out + (size_t)row * Dd;
    for (int i = threadIdx.x; i < Dd; i += blockDim.x)
        outr[i] = __float2half(xr[i] * inv * (1.f + scale[i]));
}

// ======= FP16 mma GEMM: C = A[M,Kd] @ Bt[N,Kd]^T (ldmatrix, K-tile 64) =======
constexpr int GM = 128, GN = 128, GK = 64;
constexpr int TSTRH = 72;
constexpr int STG  = 3;
constexpr int AHALF = GM * TSTRH;
constexpr int BHALF = GN * TSTRH;
constexpr int STGH  = AHALF + BHALF;
constexpr int GEMM_SMEM = STG * STGH * 2;

extern __shared__ __half dynsmem_h[];

// FOUT=1: float C (+resid). FOUT=0: half C (+optional gelu-gate multiply).
template <int FOUT>
__global__ __launch_bounds__(256, 2) void gemm_f16_kernel(
    const __half* __restrict__ A, const __half* __restrict__ Bt,
    const float* __restrict__ resid, const __half* __restrict__ gelu_src,
    void* __restrict__ Cv, int Kd, int ldc) {

    __half* smem = dynsmem_h;
    uint32_t smb = (uint32_t)__cvta_generic_to_shared(dynsmem_h);
    int m0 = blockIdx.y * GM, n0 = blockIdx.x * GN;
    int tid  = threadIdx.x;
    int lane = tid & 31, warp = tid >> 5;
    int grp = lane >> 2, tig = lane & 3;
    int wm = (warp >> 2) * 64;
    int wn = (warp & 3) * 32;

    int arow_l = (lane & 7) + ((lane >> 3) & 1) * 8;
    int acol_l = (lane >> 4) * 8;
    int brow_l = (lane & 7) + (lane >> 4) * 8;
    int bcol_l = ((lane >> 3) & 1) * 8;

    float acc[4][4][4];
    #pragma unroll
    for (int mt = 0; mt < 4; mt++)
        #pragma unroll
        for (int nt = 0; nt < 4; nt++)
            #pragma unroll
            for (int r = 0; r < 4; r++) acc[mt][nt][r] = 0.f;

    int ntile = Kd / GK;

    auto issue_tile = [&](int t) {
        int s = t % STG;
        int k0 = t * GK;
        __half* As = smem + (size_t)s * STGH;
        __half* Bs = As + AHALF;
        #pragma unroll
        for (int j = 0; j < 4; j++) {
            int c = tid + j * 256;
            int row = c >> 3, o8 = (c & 7) * 8;
            cp_async16((uint32_t)__cvta_generic_to_shared(&As[row * TSTRH + o8]),
                       &A[(size_t)(m0 + row) * Kd + k0 + o8]);
        }
        #pragma unroll
        for (int j = 0; j < 4; j++) {
            int c = tid + j * 256;
            int row = c >> 3, o8 = (c & 7) * 8;
            cp_async16((uint32_t)__cvta_generic_to_shared(&Bs[row * TSTRH + o8]),
                       &Bt[(size_t)(n0 + row) * Kd + k0 + o8]);
        }
    };

    issue_tile(0);
    asm volatile("cp.async.commit_group;");
    if (ntile > 1) issue_tile(1);
    asm volatile("cp.async.commit_group;");
    asm volatile("cp.async.wait_group 1;");
    __syncthreads();

    for (int t = 0; t < ntile; t++) {
        int s = t % STG;
        uint32_t sa = smb + (uint32_t)(s * STGH * 2);
        uint32_t aB = sa + (uint32_t)(((wm + arow_l) * TSTRH + acol_l) * 2);
        uint32_t bB = sa + (uint32_t)(AHALF * 2) +
                      (uint32_t)(((wn + brow_l) * TSTRH + bcol_l) * 2);

        if (t + 2 < ntile) issue_tile(t + 2);
        asm volatile("cp.async.commit_group;");

        #pragma unroll
        for (int kk = 0; kk < 4; kk++) {
            uint32_t af[4][4], bf[4][2];
            #pragma unroll
            for (int mt = 0; mt < 4; mt++)
                ldsm_x4(af[mt][0], af[mt][1], af[mt][2], af[mt][3],
                        aB + mt * (16 * TSTRH * 2) + kk * 32);
            #pragma unroll
            for (int ntp = 0; ntp < 2; ntp++)
                ldsm_x4(bf[2 * ntp][0], bf[2 * ntp][1], bf[2 * ntp + 1][0], bf[2 * ntp + 1][1],
                        bB + ntp * (16 * TSTRH * 2) + kk * 32);
            #pragma unroll
            for (int mt = 0; mt < 4; mt++)
                #pragma unroll
                for (int nt = 0; nt < 4; nt++)
                    mma_f16(acc[mt][nt][0], acc[mt][nt][1], acc[mt][nt][2], acc[mt][nt][3],
                            af[mt][0], af[mt][1], af[mt][2], af[mt][3],
                            bf[nt][0], bf[nt][1]);
        }

        asm volatile("cp.async.wait_group 1;");
        __syncthreads();
    }

    // epilogue
    #pragma unroll
    for (int mt = 0; mt < 4; mt++) {
        #pragma unroll
        for (int nt = 0; nt < 4; nt++) {
            int m = m0 + wm + mt * 16 + grp;
            int n = n0 + wn + nt * 8 + 2 * tig;
            float v00 = acc[mt][nt][0], v01 = acc[mt][nt][1];
            float v10 = acc[mt][nt][2], v11 = acc[mt][nt][3];
            if (FOUT) {
                float* C = (float*)Cv;
                if (resid) {
                    float2 r0 = *(const float2*)&resid[(size_t)m * ldc + n];
                    float2 r1 = *(const float2*)&resid[(size_t)(m + 8) * ldc + n];
                    v00 += r0.x; v01 += r0.y; v10 += r1.x; v11 += r1.y;
                }
                *(float2*)&C[(size_t)m * ldc + n]       = make_float2(v00, v01);
                *(float2*)&C[(size_t)(m + 8) * ldc + n] = make_float2(v10, v11);
            } else {
                __half* C = (__half*)Cv;
                if (gelu_src) {
                    __half2 h0 = *(const __half2*)&gelu_src[(size_t)m * ldc + n];
                    __half2 h1 = *(const __half2*)&gelu_src[(size_t)(m + 8) * ldc + n];
                    v00 *= gelu_f(__half2float(h0.x));
                    v01 *= gelu_f(__half2float(h0.y));
                    v10 *= gelu_f(__half2float(h1.x));
                    v11 *= gelu_f(__half2float(h1.y));
                }
                *(__half2*)&C[(size_t)m * ldc + n] =
                    __floats2half2_rn(v00, v01);
                *(__half2*)&C[(size_t)(m + 8) * ldc + n] =
                    __floats2half2_rn(v10, v11);
            }
        }
    }
}

// ---------------- RoPE (in place on combined qkv buffer) ----------------
// blockIdx.y = head index over NH + KHn (q heads then k heads). v untouched.
__global__ void rope_kernel(__half* __restrict__ qkv, const int* __restrict__ positions) {
    int row = blockIdx.x;
    int h   = blockIdx.y;
    int i   = threadIdx.x;  // 0..63
    float outscale = (h < NH) ? 0.08838834764831845f : 1.f;   // H^-0.5 for q
    int col = (h < NH) ? h * HD : NH * HD + (h - NH) * HD;
    float pos = (float)positions[row];
    float ts = powf(10000.f, (float)i / 64.f);
    float ang = pos / ts;
    float s, c;
    sincosf(ang, &s, &c);
    __half* p = qkv + (size_t)row * QKV + col;
    float x1 = __half2float(p[i]), x2 = __half2float(p[i + 64]);
    p[i]      = __float2half((x1 * c - x2 * s) * outscale);
    p[i + 64] = __float2half((x2 * c + x1 * s) * outscale);
}

// ---------------- Flash attention (fp16 mma + ldmatrix, causal) ----------
constexpr int FBQ = 64, FBS = 64;
constexpr int QKSTR = HD + 8;    // 136 halfs
constexpr int VTSTR = FBS + 8;   // 72 halfs
constexpr int PSTRH = FBS + 8;   // 72 halfs
constexpr int KOFF = NH * HD;          // 2048
constexpr int VOFF = NH * HD + KHn * HD; // 3072

__global__ __launch_bounds__(128, 2) void flash_f16_kernel(
    const __half* __restrict__ qkv) {

    int tq0 = blockIdx.x * FBQ;
    int n   = blockIdx.y;
    int b   = blockIdx.z;
    int kvh = n / GG;
    int tid  = threadIdx.x;
    int lane = tid & 31, warp = tid >> 5;
    int grp = lane >> 2, tig = lane & 3;
    int wq = warp * 16;

    __half* Qs = dynsmem_h;
    __half* Ks = Qs + FBQ * QKSTR;
    __half* Vt = Ks + FBS * QKSTR;
    __half* Ps = Vt + HD * VTSTR;
    __half* Pw = Ps + warp * 16 * PSTRH;

    int arow_l = (lane & 7) + ((lane >> 3) & 1) * 8;
    int acol_l = (lane >> 4) * 8;
    int brow_l = (lane & 7) + (lane >> 4) * 8;
    int bcol_l = ((lane >> 3) & 1) * 8;

    uint32_t qB = (uint32_t)__cvta_generic_to_shared(Qs) +
                  (uint32_t)(((wq + arow_l) * QKSTR + acol_l) * 2);
    uint32_t kB = (uint32_t)__cvta_generic_to_shared(Ks) +
                  (uint32_t)((brow_l * QKSTR + bcol_l) * 2);
    uint32_t vB = (uint32_t)__cvta_generic_to_shared(Vt) +
                  (uint32_t)((brow_l * VTSTR + bcol_l) * 2);
    uint32_t pB = (uint32_t)__cvta_generic_to_shared(Pw) +
                  (uint32_t)((arow_l * PSTRH + acol_l) * 2);

    #pragma unroll
    for (int j = 0; j < 8; j++) {
        int c = tid + j * 128;
        int row = c >> 4, o8 = (c & 15) * 8;
        cp_async16((uint32_t)__cvta_generic_to_shared(&Qs[row * QKSTR + o8]),
                   &qkv[(size_t)(b * Tt + tq0 + row) * QKV + n * HD + o8]);
    }
    asm volatile("cp.async.commit_group;");

    float m0v = -1e30f, m1v = -1e30f, l0 = 0.f, l1 = 0.f;
    float O[16][4];
    #pragma unroll
    for (int nt = 0; nt < 16; nt++)
        #pragma unroll
        for (int r = 0; r < 4; r++) O[nt][r] = 0.f;

    int ntiles = blockIdx.x + 1;
    for (int kt = 0; kt < ntiles; kt++) {
        int s0 = kt * FBS;
        __syncthreads();
        #pragma unroll
        for (int j = 0; j < 8; j++) {
            int c = tid + j * 128;
            int row = c >> 4, o8 = (c & 15) * 8;
            cp_async16((uint32_t)__cvta_generic_to_shared(&Ks[row * QKSTR + o8]),
                       &qkv[(size_t)(b * Tt + s0 + row) * QKV + KOFF + kvh * HD + o8]);
        }
        asm volatile("cp.async.commit_group;");
        #pragma unroll
        for (int j = 0; j < 8; j++) {
            int c = tid + j * 128;
            int s = c >> 4, d0 = (c & 15) * 8;
            uint4 raw = *(const uint4*)&qkv[(size_t)(b * Tt + s0 + s) * QKV + VOFF + kvh * HD + d0];
            __half hv[8];
            *(uint4*)hv = raw;
            #pragma unroll
            for (int i = 0; i < 8; i++)
                Vt[(d0 + i) * VTSTR + s] = hv[i];
        }
        asm volatile("cp.async.wait_group 0;");
        __syncthreads();

        float sc[8][4];
        #pragma unroll
        for (int nt = 0; nt < 8; nt++)
            #pragma unroll
            for (int r = 0; r < 4; r++) sc[nt][r] = 0.f;

        #pragma unroll
        for (int kk = 0; kk < 8; kk++) {
            uint32_t a0, a1, a2, a3;
            ldsm_x4(a0, a1, a2, a3, qB + kk * 32);
            uint32_t bf[8][2];
            #pragma unroll
            for (int ntp = 0; ntp < 4; ntp++)
                ldsm_x4(bf[2 * ntp][0], bf[2 * ntp][1], bf[2 * ntp + 1][0], bf[2 * ntp + 1][1],
                        kB + ntp * (16 * QKSTR * 2) + kk * 32);
            #pragma unroll
            for (int nt = 0; nt < 8; nt++)
                mma_f16(sc[nt][0], sc[nt][1], sc[nt][2], sc[nt][3],
                        a0, a1, a2, a3, bf[nt][0], bf[nt][1]);
        }

        int q0 = tq0 + wq + grp, q1 = q0 + 8;
        #pragma unroll
        for (int nt = 0; nt < 8; nt++) {
            int s = s0 + nt * 8 + 2 * tig;
            if (s     > q0) sc[nt][0] = -1e30f;
            if (s + 1 > q0) sc[nt][1] = -1e30f;
            if (s     > q1) sc[nt][2] = -1e30f;
            if (s + 1 > q1) sc[nt][3] = -1e30f;
        }

        float r0 = -1e30f, r1 = -1e30f;
        #pragma unroll
        for (int nt = 0; nt < 8; nt++) {
            r0 = fmaxf(r0, fmaxf(sc[nt][0], sc[nt][1]));
            r1 = fmaxf(r1, fmaxf(sc[nt][2], sc[nt][3]));
        }
        #pragma unroll
        for (int off = 1; off <= 2; off <<= 1) {
            r0 = fmaxf(r0, __shfl_xor_sync(0xffffffffu, r0, off));
            r1 = fmaxf(r1, __shfl_xor_sync(0xffffffffu, r1, off));
        }
        float mn0 = fmaxf(m0v, r0), mn1 = fmaxf(m1v, r1);
        float al0 = __expf(m0v - mn0), al1 = __expf(m1v - mn1);
        m0v = mn0; m1v = mn1;

        float rs0 = 0.f, rs1 = 0.f;
        uint32_t* PwU = (uint32_t*)Pw;
        #pragma unroll
        for (int nt = 0; nt < 8; nt++) {
            float p0 = __expf(sc[nt][0] - m0v);
            float p1 = __expf(sc[nt][1] - m0v);
            float p2 = __expf(sc[nt][2] - m1v);
            float p3 = __expf(sc[nt][3] - m1v);
            rs0 += p0 + p1; rs1 += p2 + p3;
            __half2 h0 = __floats2half2_rn(p0, p1);
            __half2 h1 = __floats2half2_rn(p2, p3);
            PwU[grp * 36 + nt * 4 + tig]       = *(uint32_t*)&h0;
            PwU[(grp + 8) * 36 + nt * 4 + tig] = *(uint32_t*)&h1;
        }
        #pragma unroll
        for (int off = 1; off <= 2; off <<= 1) {
            rs0 += __shfl_xor_sync(0xffffffffu, rs0, off);
            rs1 += __shfl_xor_sync(0xffffffffu, rs1, off);
        }
        l0 = l0 * al0 + rs0;
        l1 = l1 * al1 + rs1;

        #pragma unroll
        for (int nt = 0; nt < 16; nt++) {
            O[nt][0] *= al0; O[nt][1] *= al0;
            O[nt][2] *= al1; O[nt][3] *= al1;
        }

        __syncwarp();
        #pragma unroll
        for (int kk = 0; kk < 4; kk++) {
            uint32_t a0, a1, a2, a3;
            ldsm_x4(a0, a1, a2, a3, pB + kk * 32);
            #pragma unroll
            for (int ntp = 0; ntp < 8; ntp++) {
                uint32_t b00, b01, b10, b11;
                ldsm_x4(b00, b01, b10, b11,
                        vB + ntp * (16 * VTSTR * 2) + kk * 32);
                mma_f16(O[2 * ntp][0], O[2 * ntp][1], O[2 * ntp][2], O[2 * ntp][3],
                        a0, a1, a2, a3, b00, b01);
                mma_f16(O[2 * ntp + 1][0], O[2 * ntp + 1][1], O[2 * ntp + 1][2], O[2 * ntp + 1][3],
                        a0, a1, a2, a3, b10, b11);
            }
        }
    }

    float il0 = 1.f / l0, il1 = 1.f / l1;
    int qr0 = tq0 + wq + grp, qr1 = qr0 + 8;
    #pragma unroll
    for (int nt = 0; nt < 16; nt++) {
        int c = nt * 8 + 2 * tig;
        *(__half2*)&g_enc[(((size_t)b * Tt + qr0) * NH + n) * HD + c] =
            __floats2half2_rn(O[nt][0] * il0, O[nt][1] * il0);
        *(__half2*)&g_enc[(((size_t)b * Tt + qr1) * NH + n) * HD + c] =
            __floats2half2_rn(O[nt][2] * il1, O[nt][3] * il1);
    }
}

// ---------------- launch ----------------
extern "C" void kernel_launch(void* const* d_in, const int* in_sizes, int n_in,
                              void* d_out, int out_size) {
    const float* x        = (const float*)d_in[0];
    const int*   pos      = (const int*)  d_in[1];
    // d_in[2] attn_mask: causal, recomputed in-kernel
    const float* w_q      = (const float*)d_in[3];
    const float* w_kv     = (const float*)d_in[4];
    const float* w_av     = (const float*)d_in[5];
    const float* s_attn   = (const float*)d_in[6];
    const float* s_ffw    = (const float*)d_in[7];
    const float* w_gating = (const float*)d_in[8];
    const float* w_linear = (const float*)d_in[9];
    float* out = (float*)d_out;

    __half *xn, *qkvp, *encp, *hp, *gatep, *wc;
    float *resp;
    cudaGetSymbolAddress((void**)&xn,    g_xn);
    cudaGetSymbolAddress((void**)&qkvp,  g_qkv);
    cudaGetSymbolAddress((void**)&encp,  g_enc);
    cudaGetSymbolAddress((void**)&resp,  g_res);
    cudaGetSymbolAddress((void**)&hp,    g_h);
    cudaGetSymbolAddress((void**)&gatep, g_gate);
    cudaGetSymbolAddress((void**)&wc,    g_w);

    cudaFuncSetAttribute(gemm_f16_kernel<0>, cudaFuncAttributeMaxDynamicSharedMemorySize, GEMM_SMEM);
    cudaFuncSetAttribute(gemm_f16_kernel<1>, cudaFuncAttributeMaxDynamicSharedMemorySize, GEMM_SMEM);

    // 0. transpose + fp16 weights to [N][K]
    dim3 tb(32, 8);
    transpose_cvt_kernel<<<dim3(HD / 32, Dd / 32, NH),      tb>>>(w_q,      wc + WQ_OFF,  Dd, HD);
    transpose_cvt_kernel<<<dim3(HD / 32, Dd / 32, 2 * KHn), tb>>>(w_kv,     wc + WKV_OFF, Dd, HD);
    transpose_cvt_kernel<<<dim3(Dd / 32, (NH * HD) / 32, 1),tb>>>(w_av,     wc + WAV_OFF, NH * HD, Dd);
    transpose_cvt_kernel<<<dim3(FF / 32, Dd / 32, 2),       tb>>>(w_gating, wc + WG_OFF,  Dd, FF);
    transpose_cvt_kernel<<<dim3(Dd / 32, FF / 32, 1),       tb>>>(w_linear, wc + WL_OFF,  FF, Dd);

    // 1. pre-attn rmsnorm -> half
    rmsnorm_kernel<<<Mtot, 256>>>(x, s_attn, xn);

    // 2. single fused q|k|v projection (wq/wk/wv rows contiguous in g_w)
    gemm_f16_kernel<0><<<dim3(QKV / GN, Mtot / GM), 256, GEMM_SMEM>>>(
        xn, wc + WQ_OFF, nullptr, nullptr, qkvp, Dd, QKV);

    // 3. rope (q + k heads in one launch)
    rope_kernel<<<dim3(Mtot, NH + KHn), 64>>>(qkvp, pos);

    // 4. flash attention
    int fa_smem = (FBQ * QKSTR + FBS * QKSTR + HD * VTSTR + 4 * 16 * PSTRH) * 2;
    cudaFuncSetAttribute(flash_f16_kernel, cudaFuncAttributeMaxDynamicSharedMemorySize, fa_smem);
    flash_f16_kernel<<<dim3(Tt / FBQ, NH, Bc), 128, fa_smem>>>(qkvp);

    // 5. attn output proj + residual (float out)
    gemm_f16_kernel<1><<<dim3(Dd / GN, Mtot / GM), 256, GEMM_SMEM>>>(
        encp, wc + WAV_OFF, x, nullptr, resp, NH * HD, Dd);

    // 6. pre-ffw rmsnorm -> half
    rmsnorm_kernel<<<Mtot, 256>>>(resp, s_ffw, hp);

    // 7. gate GEMM, then up GEMM with fused gelu(gate)*up -> gatep (in place)
    gemm_f16_kernel<0><<<dim3(FF / GN, Mtot / GM), 256, GEMM_SMEM>>>(
        hp, wc + WG_OFF, nullptr, nullptr, gatep, Dd, FF);
    gemm_f16_kernel<0><<<dim3(FF / GN, Mtot / GM), 256, GEMM_SMEM>>>(
        hp, wc + WG_OFF + (size_t)Dd * FF, nullptr, gatep, gatep, Dd, FF);

    // 8. down proj + residual -> out (float)
    gemm_f16_kernel<1><<<dim3(Dd / GN, Mtot / GM), 256, GEMM_SMEM>>>(
        gatep, wc + WL_OFF, resp, nullptr, out, FF, Dd);
}